// round 2
// baseline (speedup 1.0000x reference)
#include <cuda_runtime.h>
#include <cstdint>

// Problem constants (fixed shapes: B=8, H=W=128, C=256, heads=8, hd=32, ws=8)
#define NTOK  131072          // B * H * W = 8*16384
#define CDIM  256
#define NHEAD 8
#define HD    32

// Scratch in device globals (allocation-free rule)
__device__ float g_pe[64 * 256];                     // PE table: 64 window positions x 256 ch
__device__ float g_Q[(size_t)NTOK * CDIM];
__device__ float g_K[(size_t)NTOK * CDIM];
__device__ float g_V[(size_t)NTOK * CDIM];
__device__ float g_O[(size_t)NTOK * CDIM];

// ---------------------------------------------------------------------------
// PE table: pe[p][c], p = wy*8+wx, channels [sin(px f), cos(px f), sin(py f), cos(py f)]
// px = 3.14 * x * f / 200
// ---------------------------------------------------------------------------
__global__ void pe_init_kernel() {
    int idx = blockIdx.x * 256 + threadIdx.x;   // 16384 total
    int p = idx >> 8, c = idx & 255;
    int wy = p >> 3, wx = p & 7;
    int f = c & 63, quad = c >> 6;
    float coord = (quad < 2) ? (float)wx : (float)wy;
    float arg = 3.14f * coord * (float)f * (1.0f / 200.0f);
    g_pe[idx] = (quad & 1) ? cosf(arg) : sinf(arg);
}

// ---------------------------------------------------------------------------
// tf32 helpers
// ---------------------------------------------------------------------------
__device__ __forceinline__ uint32_t f2tf(float x) {
    uint32_t r;
    asm("cvt.rna.tf32.f32 %0, %1;" : "=r"(r) : "f"(x));
    return r;
}

__device__ __forceinline__ void mma_tf32(float& c0, float& c1, float& c2, float& c3,
                                         uint32_t a0, uint32_t a1, uint32_t a2, uint32_t a3,
                                         uint32_t b0, uint32_t b1) {
    asm volatile(
        "mma.sync.aligned.m16n8k8.row.col.f32.tf32.tf32.f32 "
        "{%0,%1,%2,%3}, {%4,%5,%6,%7}, {%8,%9}, {%0,%1,%2,%3};\n"
        : "+f"(c0), "+f"(c1), "+f"(c2), "+f"(c3)
        : "r"(a0), "r"(a1), "r"(a2), "r"(a3), "r"(b0), "r"(b1));
}

// ---------------------------------------------------------------------------
// GEMM: C[m][n] = sum_k A[m][k] * W[n][k] + bias[n]
// M = 131072, N = K = 256. Block tile 128x128, K-chunk 32.
// ADD_PE: A element gets + g_pe[window_pos(row)][k] (fused x+pe for Q/K).
// ---------------------------------------------------------------------------
template <bool ADD_PE>
__global__ void __launch_bounds__(256) gemm256_kernel(const float* __restrict__ A,
                                                      const float* __restrict__ Wt,
                                                      const float* __restrict__ bias,
                                                      float* __restrict__ C) {
    __shared__ float As[128][36];   // pad 36: stride mod 32 = 4 -> conflict-free frags
    __shared__ float Bs[128][36];

    int tid = threadIdx.x;
    int lane = tid & 31, warp = tid >> 5;
    int wm = (warp & 1) * 64;        // 2 warps along M
    int wn = (warp >> 1) * 32;       // 4 warps along N
    long mBase = (long)blockIdx.x * 128;
    int nBase = blockIdx.y * 128;

    float acc[4][4][4];
#pragma unroll
    for (int i = 0; i < 4; i++)
#pragma unroll
        for (int j = 0; j < 4; j++)
#pragma unroll
            for (int r = 0; r < 4; r++) acc[i][j][r] = 0.f;

    for (int k0 = 0; k0 < 256; k0 += 32) {
        // Load A (128x32) and B (128x32) tiles, vectorized
#pragma unroll
        for (int i = 0; i < 4; i++) {
            int idx = tid + i * 256;            // 0..1023
            int row = idx >> 3;
            int cs = (idx & 7) << 2;
            float4 v = *(const float4*)(A + (mBase + row) * 256 + k0 + cs);
            if (ADD_PE) {
                int token = (int)((mBase + row) & 16383);
                int gy = token >> 7, gx = token & 127;
                int prow = ((gy & 7) << 3) | (gx & 7);
                float4 pe = *(const float4*)(g_pe + prow * 256 + k0 + cs);
                v.x += pe.x; v.y += pe.y; v.z += pe.z; v.w += pe.w;
            }
            *(float4*)(&As[row][cs]) = v;
            float4 w = *(const float4*)(Wt + (nBase + row) * 256 + k0 + cs);
            *(float4*)(&Bs[row][cs]) = w;
        }
        __syncthreads();

#pragma unroll
        for (int ks = 0; ks < 4; ks++) {
            int kb = ks * 8;
            uint32_t af[4][4], bf[4][2];
#pragma unroll
            for (int mi = 0; mi < 4; mi++) {
                int r = wm + mi * 16 + (lane >> 2);
                int c = kb + (lane & 3);
                af[mi][0] = f2tf(As[r][c]);
                af[mi][1] = f2tf(As[r + 8][c]);
                af[mi][2] = f2tf(As[r][c + 4]);
                af[mi][3] = f2tf(As[r + 8][c + 4]);
            }
#pragma unroll
            for (int ni = 0; ni < 4; ni++) {
                int n = wn + ni * 8 + (lane >> 2);
                int c = kb + (lane & 3);
                bf[ni][0] = f2tf(Bs[n][c]);
                bf[ni][1] = f2tf(Bs[n][c + 4]);
            }
#pragma unroll
            for (int mi = 0; mi < 4; mi++)
#pragma unroll
                for (int ni = 0; ni < 4; ni++)
                    mma_tf32(acc[mi][ni][0], acc[mi][ni][1], acc[mi][ni][2], acc[mi][ni][3],
                             af[mi][0], af[mi][1], af[mi][2], af[mi][3],
                             bf[ni][0], bf[ni][1]);
        }
        __syncthreads();
    }

    // Epilogue: add bias, write float2 pairs
#pragma unroll
    for (int mi = 0; mi < 4; mi++) {
        long r = mBase + wm + mi * 16 + (lane >> 2);
#pragma unroll
        for (int ni = 0; ni < 4; ni++) {
            int col = nBase + wn + ni * 8 + ((lane & 3) << 1);
            float b0 = __ldg(bias + col);
            float b1 = __ldg(bias + col + 1);
            *(float2*)(C + r * 256 + col) =
                make_float2(acc[mi][ni][0] + b0, acc[mi][ni][1] + b1);
            *(float2*)(C + (r + 8) * 256 + col) =
                make_float2(acc[mi][ni][2] + b0, acc[mi][ni][3] + b1);
        }
    }
}

// ---------------------------------------------------------------------------
// Attention: one block per (batch, window, head). 4 warps.
// S = QK^T * scale -> softmax -> O = P V, all via tf32 mma.
// ---------------------------------------------------------------------------
__global__ void __launch_bounds__(128) attn_kernel() {
    __shared__ float Qs[64][36], Ks[64][36], Vs[64][36];
    __shared__ float Ss[64][68];

    int tid = threadIdx.x, lane = tid & 31, warp = tid >> 5;
    int head = blockIdx.x & 7;
    int win = blockIdx.x >> 3;
    int b = win >> 8;
    int wl = win & 255;
    int wyi = wl >> 4, wxi = wl & 15;
    long base = (long)b * 16384;

    // Load Q/K/V head slices: 64 rows x 32 ch each
#pragma unroll
    for (int i = 0; i < 4; i++) {
        int idx = tid + i * 128;                // 0..511
        int p = idx >> 3;
        int cs = (idx & 7) << 2;
        int gy = wyi * 8 + (p >> 3);
        int gx = wxi * 8 + (p & 7);
        long off = (base + gy * 128 + gx) * 256 + head * 32 + cs;
        *(float4*)(&Qs[p][cs]) = *(const float4*)(g_Q + off);
        *(float4*)(&Ks[p][cs]) = *(const float4*)(g_K + off);
        *(float4*)(&Vs[p][cs]) = *(const float4*)(g_V + off);
    }
    __syncthreads();

    // S: warp w owns rows [16w,16w+16), all 64 cols (8 n-frags), K=32 (4 steps)
    float sc[8][4];
#pragma unroll
    for (int nf = 0; nf < 8; nf++)
#pragma unroll
        for (int r = 0; r < 4; r++) sc[nf][r] = 0.f;

#pragma unroll
    for (int kk = 0; kk < 32; kk += 8) {
        int r0 = 16 * warp + (lane >> 2);
        int cA = kk + (lane & 3);
        uint32_t a0 = f2tf(Qs[r0][cA]);
        uint32_t a1 = f2tf(Qs[r0 + 8][cA]);
        uint32_t a2 = f2tf(Qs[r0][cA + 4]);
        uint32_t a3 = f2tf(Qs[r0 + 8][cA + 4]);
#pragma unroll
        for (int nf = 0; nf < 8; nf++) {
            int n = nf * 8 + (lane >> 2);
            uint32_t b0 = f2tf(Ks[n][cA]);
            uint32_t b1 = f2tf(Ks[n][cA + 4]);
            mma_tf32(sc[nf][0], sc[nf][1], sc[nf][2], sc[nf][3], a0, a1, a2, a3, b0, b1);
        }
    }

    // Softmax over rows r0 = 16w + lane/4 and r1 = r0+8 (4 lanes per row)
    const float scale = 0.17677669529663687f;   // 1/sqrt(32)
    float m0 = -1e30f, m1 = -1e30f;
#pragma unroll
    for (int nf = 0; nf < 8; nf++) {
        m0 = fmaxf(m0, fmaxf(sc[nf][0], sc[nf][1]));
        m1 = fmaxf(m1, fmaxf(sc[nf][2], sc[nf][3]));
    }
    m0 = fmaxf(m0, __shfl_xor_sync(0xffffffffu, m0, 1));
    m0 = fmaxf(m0, __shfl_xor_sync(0xffffffffu, m0, 2));
    m1 = fmaxf(m1, __shfl_xor_sync(0xffffffffu, m1, 1));
    m1 = fmaxf(m1, __shfl_xor_sync(0xffffffffu, m1, 2));

    float s0 = 0.f, s1 = 0.f;
#pragma unroll
    for (int nf = 0; nf < 8; nf++) {
        sc[nf][0] = __expf(scale * (sc[nf][0] - m0));
        sc[nf][1] = __expf(scale * (sc[nf][1] - m0));
        sc[nf][2] = __expf(scale * (sc[nf][2] - m1));
        sc[nf][3] = __expf(scale * (sc[nf][3] - m1));
        s0 += sc[nf][0] + sc[nf][1];
        s1 += sc[nf][2] + sc[nf][3];
    }
    s0 += __shfl_xor_sync(0xffffffffu, s0, 1);
    s0 += __shfl_xor_sync(0xffffffffu, s0, 2);
    s1 += __shfl_xor_sync(0xffffffffu, s1, 1);
    s1 += __shfl_xor_sync(0xffffffffu, s1, 2);
    float inv0 = 1.0f / s0, inv1 = 1.0f / s1;

    {
        int r0 = 16 * warp + (lane >> 2);
        int r1 = r0 + 8;
#pragma unroll
        for (int nf = 0; nf < 8; nf++) {
            int c = nf * 8 + ((lane & 3) << 1);
            Ss[r0][c] = sc[nf][0] * inv0;
            Ss[r0][c + 1] = sc[nf][1] * inv0;
            Ss[r1][c] = sc[nf][2] * inv1;
            Ss[r1][c + 1] = sc[nf][3] * inv1;
        }
    }
    __syncwarp();   // P rows for warp w's second mma are produced by warp w itself

    // O = P @ V: warp w rows [16w,16w+16), cols 0..31 (4 n-frags), K=64 (8 steps)
    float oc[4][4];
#pragma unroll
    for (int nf = 0; nf < 4; nf++)
#pragma unroll
        for (int r = 0; r < 4; r++) oc[nf][r] = 0.f;

#pragma unroll
    for (int kk = 0; kk < 64; kk += 8) {
        int ra = 16 * warp + (lane >> 2);
        int cA = kk + (lane & 3);
        uint32_t a0 = f2tf(Ss[ra][cA]);
        uint32_t a1 = f2tf(Ss[ra + 8][cA]);
        uint32_t a2 = f2tf(Ss[ra][cA + 4]);
        uint32_t a3 = f2tf(Ss[ra + 8][cA + 4]);
#pragma unroll
        for (int nf = 0; nf < 4; nf++) {
            int n = nf * 8 + (lane >> 2);
            uint32_t b0 = f2tf(Vs[kk + (lane & 3)][n]);
            uint32_t b1 = f2tf(Vs[kk + (lane & 3) + 4][n]);
            mma_tf32(oc[nf][0], oc[nf][1], oc[nf][2], oc[nf][3], a0, a1, a2, a3, b0, b1);
        }
    }

    // Write O back to token-major layout
    {
        int p0 = 16 * warp + (lane >> 2);
        int p1 = p0 + 8;
        int gy0 = wyi * 8 + (p0 >> 3), gx0 = wxi * 8 + (p0 & 7);
        int gy1 = wyi * 8 + (p1 >> 3), gx1 = wxi * 8 + (p1 & 7);
        long row0 = base + gy0 * 128 + gx0;
        long row1 = base + gy1 * 128 + gx1;
#pragma unroll
        for (int nf = 0; nf < 4; nf++) {
            int col = head * 32 + nf * 8 + ((lane & 3) << 1);
            *(float2*)(g_O + row0 * 256 + col) = make_float2(oc[nf][0], oc[nf][1]);
            *(float2*)(g_O + row1 * 256 + col) = make_float2(oc[nf][2], oc[nf][3]);
        }
    }
}

// ---------------------------------------------------------------------------
// Launch
// ---------------------------------------------------------------------------
extern "C" void kernel_launch(void* const* d_in, const int* in_sizes, int n_in,
                              void* d_out, int out_size) {
    const float* x  = (const float*)d_in[0];
    const float* Wq = (const float*)d_in[1];
    const float* bq = (const float*)d_in[2];
    const float* Wk = (const float*)d_in[3];
    const float* bk = (const float*)d_in[4];
    const float* Wv = (const float*)d_in[5];
    const float* bv = (const float*)d_in[6];
    const float* Wp = (const float*)d_in[7];
    const float* bp = (const float*)d_in[8];
    float* out = (float*)d_out;

    float *Q, *K, *V, *O;
    cudaGetSymbolAddress((void**)&Q, g_Q);
    cudaGetSymbolAddress((void**)&K, g_K);
    cudaGetSymbolAddress((void**)&V, g_V);
    cudaGetSymbolAddress((void**)&O, g_O);

    pe_init_kernel<<<64, 256>>>();

    dim3 gg(NTOK / 128, 2);
    gemm256_kernel<true><<<gg, 256>>>(x, Wq, bq, Q);
    gemm256_kernel<true><<<gg, 256>>>(x, Wk, bk, K);
    gemm256_kernel<false><<<gg, 256>>>(x, Wv, bv, V);

    // 2048 windows (8 batches x 16x16 window grid) x 8 heads = 16384 blocks
    attn_kernel<<<2048 * NHEAD, 128>>>();

    gemm256_kernel<false><<<gg, 256>>>(O, Wp, bp, out);
}

// round 3
// speedup vs baseline: 1.0604x; 1.0604x over previous
#include <cuda_runtime.h>
#include <cstdint>

// Fixed shapes: B=8, H=W=128, C=256, heads=8, hd=32, ws=8
#define NTOK  131072
#define NHEAD 8

// Scratch (allocation-free rule: device globals)
__device__ float g_Q[(size_t)NTOK * 256];
__device__ float g_K[(size_t)NTOK * 256];
__device__ float g_V[(size_t)NTOK * 256];
__device__ float g_O[(size_t)NTOK * 256];
__device__ float g_tab[3][64][256];   // [q|k|v] epilogue tables: pe@W^T + b (v: just bias)

// ---------------------------------------------------------------------------
// helpers
// ---------------------------------------------------------------------------
__device__ __forceinline__ uint32_t f2tf(float x) {
    uint32_t r;
    asm("cvt.rna.tf32.f32 %0, %1;" : "=r"(r) : "f"(x));
    return r;
}

__device__ __forceinline__ void mma_tf32(float& c0, float& c1, float& c2, float& c3,
                                         uint32_t a0, uint32_t a1, uint32_t a2, uint32_t a3,
                                         uint32_t b0, uint32_t b1) {
    asm volatile(
        "mma.sync.aligned.m16n8k8.row.col.f32.tf32.tf32.f32 "
        "{%0,%1,%2,%3}, {%4,%5,%6,%7}, {%8,%9}, {%0,%1,%2,%3};\n"
        : "+f"(c0), "+f"(c1), "+f"(c2), "+f"(c3)
        : "r"(a0), "r"(a1), "r"(a2), "r"(a3), "r"(b0), "r"(b1));
}

__device__ __forceinline__ void cp16(uint32_t smem, const float* gmem) {
    asm volatile("cp.async.cg.shared.global [%0], [%1], 16;" :: "r"(smem), "l"(gmem));
}

// ---------------------------------------------------------------------------
// prep: g_tab[0] = pe @ Wq^T + bq, g_tab[1] = pe @ Wk^T + bk, g_tab[2] = bv.
// One block per window position p (64), one thread per out channel n (256).
// ---------------------------------------------------------------------------
__global__ void prep_kernel(const float* __restrict__ Wq, const float* __restrict__ bq,
                            const float* __restrict__ Wk, const float* __restrict__ bk,
                            const float* __restrict__ bv) {
    __shared__ float per[256];
    int p = blockIdx.x, n = threadIdx.x;
    int wy = p >> 3, wx = p & 7;
    {   // FlowFormer LinearPositionEmbeddingSine channel layout
        int f = n & 63, quad = n >> 6;
        float coord = (quad < 2) ? (float)wx : (float)wy;
        float arg = 3.14f * coord * (float)f * (1.0f / 200.0f);
        per[n] = (quad & 1) ? cosf(arg) : sinf(arg);
    }
    __syncthreads();
    float sq = bq[n], sk = bk[n];
    const float* wq = Wq + (size_t)n * 256;
    const float* wk = Wk + (size_t)n * 256;
#pragma unroll 8
    for (int k = 0; k < 256; k++) {
        float pv = per[k];
        sq = fmaf(pv, wq[k], sq);
        sk = fmaf(pv, wk[k], sk);
    }
    g_tab[0][p][n] = sq;
    g_tab[1][p][n] = sk;
    g_tab[2][p][n] = bv[n];
}

// ---------------------------------------------------------------------------
// GEMM: C[m][n] = sum_k A[m][k] * W[n][k] (+ table/bias).
// M = 131072, K = 256. Block tile 128x128, k-chunk 32, cp.async double-buffered.
// MODE 0: fused QKV, grid.y in [0,6): y>>1 selects matrix, y&1 selects n-block;
//         epilogue adds g_tab[mat][window_pos][col].
// MODE 1: plain GEMM + bias (projection), grid.y in [0,2).
// ---------------------------------------------------------------------------
template <int MODE>
__global__ void __launch_bounds__(256, 2) gemm_kernel(
        const float* __restrict__ A,
        const float* __restrict__ W0, const float* __restrict__ W1, const float* __restrict__ W2,
        const float* __restrict__ bias,
        float* __restrict__ C0, float* __restrict__ C1, float* __restrict__ C2) {
    extern __shared__ float sm[];   // As: [2][128][36], Bs at +9216: [2][128][36]
    int tid = threadIdx.x, lane = tid & 31, warp = tid >> 5;
    int wm = (warp & 1) * 64;
    int wn = (warp >> 1) * 32;
    long mBase = (long)blockIdx.x * 128;
    int y = blockIdx.y;
    int mat = (MODE == 0) ? (y >> 1) : 0;
    int nb = (y & 1) * 128;
    const float* W = ((MODE == 0) ? (mat == 0 ? W0 : (mat == 1 ? W1 : W2)) : W0) + (size_t)nb * 256;
    float* C = (MODE == 0) ? (mat == 0 ? C0 : (mat == 1 ? C1 : C2)) : C0;

    uint32_t smBase = (uint32_t)__cvta_generic_to_shared(sm);

    float acc[4][4][4] = {};

    auto load_chunk = [&](int k0, int buf) {
#pragma unroll
        for (int i = 0; i < 4; i++) {
            int idx = tid + i * 256;            // 0..1023
            int row = idx >> 3;
            int cs = (idx & 7) << 2;
            cp16(smBase + (uint32_t)(buf * 4608 + row * 36 + cs) * 4,
                 A + (mBase + row) * 256 + k0 + cs);
            cp16(smBase + (uint32_t)(9216 + buf * 4608 + row * 36 + cs) * 4,
                 W + (size_t)row * 256 + k0 + cs);
        }
        asm volatile("cp.async.commit_group;");
    };

    load_chunk(0, 0);
    for (int c = 0; c < 8; c++) {
        int cur = c & 1;
        if (c < 7) {
            load_chunk((c + 1) * 32, cur ^ 1);
            asm volatile("cp.async.wait_group 1;");
        } else {
            asm volatile("cp.async.wait_group 0;");
        }
        __syncthreads();
        const float* As_ = sm + cur * 4608;
        const float* Bs_ = sm + 9216 + cur * 4608;
#pragma unroll
        for (int ks = 0; ks < 4; ks++) {
            int kb = ks * 8;
            uint32_t af[4][4], bf[4][2];
#pragma unroll
            for (int mi = 0; mi < 4; mi++) {
                int r = wm + mi * 16 + (lane >> 2);
                int cc = kb + (lane & 3);
                af[mi][0] = f2tf(As_[r * 36 + cc]);
                af[mi][1] = f2tf(As_[(r + 8) * 36 + cc]);
                af[mi][2] = f2tf(As_[r * 36 + cc + 4]);
                af[mi][3] = f2tf(As_[(r + 8) * 36 + cc + 4]);
            }
#pragma unroll
            for (int ni = 0; ni < 4; ni++) {
                int n = wn + ni * 8 + (lane >> 2);
                int cc = kb + (lane & 3);
                bf[ni][0] = f2tf(Bs_[n * 36 + cc]);
                bf[ni][1] = f2tf(Bs_[n * 36 + cc + 4]);
            }
#pragma unroll
            for (int mi = 0; mi < 4; mi++)
#pragma unroll
                for (int ni = 0; ni < 4; ni++)
                    mma_tf32(acc[mi][ni][0], acc[mi][ni][1], acc[mi][ni][2], acc[mi][ni][3],
                             af[mi][0], af[mi][1], af[mi][2], af[mi][3],
                             bf[ni][0], bf[ni][1]);
        }
        __syncthreads();
    }

    // Epilogue. Block's 128 rows = one image row -> gy const; (gx+8)&7 == gx&7,
    // so both fragment rows share the same table row.
    int gyb = (int)((mBase >> 7) & 7);
#pragma unroll
    for (int mi = 0; mi < 4; mi++) {
        int rl = wm + mi * 16 + (lane >> 2);
        long r0 = mBase + rl;
#pragma unroll
        for (int ni = 0; ni < 4; ni++) {
            int col = nb + wn + ni * 8 + ((lane & 3) << 1);
            float2 t;
            if (MODE == 0) {
                int p = gyb * 8 + (rl & 7);
                t = *(const float2*)&g_tab[mat][p][col];
            } else {
                t = make_float2(__ldg(bias + col), __ldg(bias + col + 1));
            }
            *(float2*)(C + r0 * 256 + col) =
                make_float2(acc[mi][ni][0] + t.x, acc[mi][ni][1] + t.y);
            *(float2*)(C + (r0 + 8) * 256 + col) =
                make_float2(acc[mi][ni][2] + t.x, acc[mi][ni][3] + t.y);
        }
    }
}

// ---------------------------------------------------------------------------
// Attention: one block per (batch, window, head). 4 warps. Unchanged from R2.
// ---------------------------------------------------------------------------
__global__ void __launch_bounds__(128) attn_kernel() {
    __shared__ float Qs[64][36], Ks[64][36], Vs[64][36];
    __shared__ float Ss[64][68];

    int tid = threadIdx.x, lane = tid & 31, warp = tid >> 5;
    int head = blockIdx.x & 7;
    int win = blockIdx.x >> 3;
    int b = win >> 8;
    int wl = win & 255;
    int wyi = wl >> 4, wxi = wl & 15;
    long base = (long)b * 16384;

#pragma unroll
    for (int i = 0; i < 4; i++) {
        int idx = tid + i * 128;
        int p = idx >> 3;
        int cs = (idx & 7) << 2;
        int gy = wyi * 8 + (p >> 3);
        int gx = wxi * 8 + (p & 7);
        long off = (base + gy * 128 + gx) * 256 + head * 32 + cs;
        *(float4*)(&Qs[p][cs]) = *(const float4*)(g_Q + off);
        *(float4*)(&Ks[p][cs]) = *(const float4*)(g_K + off);
        *(float4*)(&Vs[p][cs]) = *(const float4*)(g_V + off);
    }
    __syncthreads();

    float sc[8][4];
#pragma unroll
    for (int nf = 0; nf < 8; nf++)
#pragma unroll
        for (int r = 0; r < 4; r++) sc[nf][r] = 0.f;

#pragma unroll
    for (int kk = 0; kk < 32; kk += 8) {
        int r0 = 16 * warp + (lane >> 2);
        int cA = kk + (lane & 3);
        uint32_t a0 = f2tf(Qs[r0][cA]);
        uint32_t a1 = f2tf(Qs[r0 + 8][cA]);
        uint32_t a2 = f2tf(Qs[r0][cA + 4]);
        uint32_t a3 = f2tf(Qs[r0 + 8][cA + 4]);
#pragma unroll
        for (int nf = 0; nf < 8; nf++) {
            int n = nf * 8 + (lane >> 2);
            uint32_t b0 = f2tf(Ks[n][cA]);
            uint32_t b1 = f2tf(Ks[n][cA + 4]);
            mma_tf32(sc[nf][0], sc[nf][1], sc[nf][2], sc[nf][3], a0, a1, a2, a3, b0, b1);
        }
    }

    const float scale = 0.17677669529663687f;   // 1/sqrt(32)
    float m0 = -1e30f, m1 = -1e30f;
#pragma unroll
    for (int nf = 0; nf < 8; nf++) {
        m0 = fmaxf(m0, fmaxf(sc[nf][0], sc[nf][1]));
        m1 = fmaxf(m1, fmaxf(sc[nf][2], sc[nf][3]));
    }
    m0 = fmaxf(m0, __shfl_xor_sync(0xffffffffu, m0, 1));
    m0 = fmaxf(m0, __shfl_xor_sync(0xffffffffu, m0, 2));
    m1 = fmaxf(m1, __shfl_xor_sync(0xffffffffu, m1, 1));
    m1 = fmaxf(m1, __shfl_xor_sync(0xffffffffu, m1, 2));

    float s0 = 0.f, s1 = 0.f;
#pragma unroll
    for (int nf = 0; nf < 8; nf++) {
        sc[nf][0] = __expf(scale * (sc[nf][0] - m0));
        sc[nf][1] = __expf(scale * (sc[nf][1] - m0));
        sc[nf][2] = __expf(scale * (sc[nf][2] - m1));
        sc[nf][3] = __expf(scale * (sc[nf][3] - m1));
        s0 += sc[nf][0] + sc[nf][1];
        s1 += sc[nf][2] + sc[nf][3];
    }
    s0 += __shfl_xor_sync(0xffffffffu, s0, 1);
    s0 += __shfl_xor_sync(0xffffffffu, s0, 2);
    s1 += __shfl_xor_sync(0xffffffffu, s1, 1);
    s1 += __shfl_xor_sync(0xffffffffu, s1, 2);
    float inv0 = 1.0f / s0, inv1 = 1.0f / s1;

    {
        int r0 = 16 * warp + (lane >> 2);
        int r1 = r0 + 8;
#pragma unroll
        for (int nf = 0; nf < 8; nf++) {
            int c = nf * 8 + ((lane & 3) << 1);
            Ss[r0][c] = sc[nf][0] * inv0;
            Ss[r0][c + 1] = sc[nf][1] * inv0;
            Ss[r1][c] = sc[nf][2] * inv1;
            Ss[r1][c + 1] = sc[nf][3] * inv1;
        }
    }
    __syncwarp();

    float oc[4][4];
#pragma unroll
    for (int nf = 0; nf < 4; nf++)
#pragma unroll
        for (int r = 0; r < 4; r++) oc[nf][r] = 0.f;

#pragma unroll
    for (int kk = 0; kk < 64; kk += 8) {
        int ra = 16 * warp + (lane >> 2);
        int cA = kk + (lane & 3);
        uint32_t a0 = f2tf(Ss[ra][cA]);
        uint32_t a1 = f2tf(Ss[ra + 8][cA]);
        uint32_t a2 = f2tf(Ss[ra][cA + 4]);
        uint32_t a3 = f2tf(Ss[ra + 8][cA + 4]);
#pragma unroll
        for (int nf = 0; nf < 4; nf++) {
            int n = nf * 8 + (lane >> 2);
            uint32_t b0 = f2tf(Vs[kk + (lane & 3)][n]);
            uint32_t b1 = f2tf(Vs[kk + (lane & 3) + 4][n]);
            mma_tf32(oc[nf][0], oc[nf][1], oc[nf][2], oc[nf][3], a0, a1, a2, a3, b0, b1);
        }
    }

    {
        int p0 = 16 * warp + (lane >> 2);
        int p1 = p0 + 8;
        int gy0 = wyi * 8 + (p0 >> 3), gx0 = wxi * 8 + (p0 & 7);
        int gy1 = wyi * 8 + (p1 >> 3), gx1 = wxi * 8 + (p1 & 7);
        long row0 = base + gy0 * 128 + gx0;
        long row1 = base + gy1 * 128 + gx1;
#pragma unroll
        for (int nf = 0; nf < 4; nf++) {
            int col = head * 32 + nf * 8 + ((lane & 3) << 1);
            *(float2*)(g_O + row0 * 256 + col) = make_float2(oc[nf][0], oc[nf][1]);
            *(float2*)(g_O + row1 * 256 + col) = make_float2(oc[nf][2], oc[nf][3]);
        }
    }
}

// ---------------------------------------------------------------------------
// Launch
// ---------------------------------------------------------------------------
extern "C" void kernel_launch(void* const* d_in, const int* in_sizes, int n_in,
                              void* d_out, int out_size) {
    const float* x  = (const float*)d_in[0];
    const float* Wq = (const float*)d_in[1];
    const float* bq = (const float*)d_in[2];
    const float* Wk = (const float*)d_in[3];
    const float* bk = (const float*)d_in[4];
    const float* Wv = (const float*)d_in[5];
    const float* bv = (const float*)d_in[6];
    const float* Wp = (const float*)d_in[7];
    const float* bp = (const float*)d_in[8];
    float* out = (float*)d_out;

    float *Q, *K, *V, *O;
    cudaGetSymbolAddress((void**)&Q, g_Q);
    cudaGetSymbolAddress((void**)&K, g_K);
    cudaGetSymbolAddress((void**)&V, g_V);
    cudaGetSymbolAddress((void**)&O, g_O);

    const int SMEM = 2 * (4608 + 4608) * 4;   // 73728 B
    cudaFuncSetAttribute(gemm_kernel<0>, cudaFuncAttributeMaxDynamicSharedMemorySize, SMEM);
    cudaFuncSetAttribute(gemm_kernel<1>, cudaFuncAttributeMaxDynamicSharedMemorySize, SMEM);

    prep_kernel<<<64, 256>>>(Wq, bq, Wk, bk, bv);

    gemm_kernel<0><<<dim3(NTOK / 128, 6), 256, SMEM>>>(x, Wq, Wk, Wv, nullptr, Q, K, V);

    attn_kernel<<<2048 * NHEAD, 128>>>();

    gemm_kernel<1><<<dim3(NTOK / 128, 2), 256, SMEM>>>(O, Wp, nullptr, nullptr, bp,
                                                       out, nullptr, nullptr);
}

// round 5
// speedup vs baseline: 1.3422x; 1.2657x over previous
#include <cuda_runtime.h>
#include <cuda_fp16.h>
#include <cstdint>

// Fixed shapes: B=8, H=W=128, C=256, heads=8, hd=32, ws=8
#define NTOK  131072
#define NHEAD 8

// Scratch (allocation-free rule: device globals)
__device__ float g_Q[(size_t)NTOK * 256];
__device__ float g_K[(size_t)NTOK * 256];
__device__ float g_V[(size_t)NTOK * 256];
__device__ float g_O[(size_t)NTOK * 256];
__device__ float g_tab[3][64][256];   // q/k: pe@W^T + b ; v: bias

// ---------------------------------------------------------------------------
// helpers
// ---------------------------------------------------------------------------
__device__ __forceinline__ uint32_t f2tf(float x) {
    uint32_t r;
    asm("cvt.rna.tf32.f32 %0, %1;" : "=r"(r) : "f"(x));
    return r;
}

__device__ __forceinline__ void mma_tf32(float& c0, float& c1, float& c2, float& c3,
                                         uint32_t a0, uint32_t a1, uint32_t a2, uint32_t a3,
                                         uint32_t b0, uint32_t b1) {
    asm volatile(
        "mma.sync.aligned.m16n8k8.row.col.f32.tf32.tf32.f32 "
        "{%0,%1,%2,%3}, {%4,%5,%6,%7}, {%8,%9}, {%0,%1,%2,%3};\n"
        : "+f"(c0), "+f"(c1), "+f"(c2), "+f"(c3)
        : "r"(a0), "r"(a1), "r"(a2), "r"(a3), "r"(b0), "r"(b1));
}

__device__ __forceinline__ void mma_f16(float& c0, float& c1, float& c2, float& c3,
                                        uint32_t a0, uint32_t a1, uint32_t a2, uint32_t a3,
                                        uint32_t b0, uint32_t b1) {
    asm volatile(
        "mma.sync.aligned.m16n8k16.row.col.f32.f16.f16.f32 "
        "{%0,%1,%2,%3}, {%4,%5,%6,%7}, {%8,%9}, {%0,%1,%2,%3};\n"
        : "+f"(c0), "+f"(c1), "+f"(c2), "+f"(c3)
        : "r"(a0), "r"(a1), "r"(a2), "r"(a3), "r"(b0), "r"(b1));
}

__device__ __forceinline__ void ldsm4(uint32_t& r0, uint32_t& r1, uint32_t& r2, uint32_t& r3,
                                      uint32_t addr) {
    asm volatile("ldmatrix.sync.aligned.m8n8.x4.shared.b16 {%0,%1,%2,%3}, [%4];"
                 : "=r"(r0), "=r"(r1), "=r"(r2), "=r"(r3) : "r"(addr));
}

__device__ __forceinline__ uint32_t smem_u32(const void* p) {
    uint32_t a;
    asm("{ .reg .u64 t; cvta.to.shared.u64 t, %1; cvt.u32.u64 %0, t; }" : "=r"(a) : "l"(p));
    return a;
}

// ---------------------------------------------------------------------------
// prep: g_tab[0] = pe@Wq^T+bq, g_tab[1] = pe@Wk^T+bk, g_tab[2] = bv
// ---------------------------------------------------------------------------
__global__ void prep_kernel(const float* __restrict__ Wq, const float* __restrict__ bq,
                            const float* __restrict__ Wk, const float* __restrict__ bk,
                            const float* __restrict__ bv) {
    __shared__ float per[256];
    int p = blockIdx.x, n = threadIdx.x;
    int wy = p >> 3, wx = p & 7;
    {
        int f = n & 63, quad = n >> 6;
        float coord = (quad < 2) ? (float)wx : (float)wy;
        float arg = 3.14f * coord * (float)f * (1.0f / 200.0f);
        per[n] = (quad & 1) ? cosf(arg) : sinf(arg);
    }
    __syncthreads();
    float sq = bq[n], sk = bk[n];
    const float* wq = Wq + (size_t)n * 256;
    const float* wk = Wk + (size_t)n * 256;
#pragma unroll 8
    for (int k = 0; k < 256; k++) {
        float pv = per[k];
        sq = fmaf(pv, wq[k], sq);
        sk = fmaf(pv, wk[k], sk);
    }
    g_tab[0][p][n] = sq;
    g_tab[1][p][n] = sk;
    g_tab[2][p][n] = bv[n];
}

// ---------------------------------------------------------------------------
// fp16 GEMM (legacy HMMA.16816 + ldmatrix).
// C_m[row][n] = sum_k A[row][k] * W_m[n][k] (+ table/bias).
// Block: 128 M-rows x 128 N-cols.  A fp16 fully resident [128][264];
// B fp16 double-buffered [2][128][40] per 32-k chunk (register-staged LDG).
// NMAT=3: loops Q,K,V reusing resident A; epilogue adds g_tab[m][pos][col].
// NMAT=1: projection; epilogue adds bias.
// ---------------------------------------------------------------------------
#define AH_STRIDE 264            // halves; 528B row stride -> ldmatrix conflict-free
#define BH_STRIDE 40             // halves;  80B row stride -> ldmatrix conflict-free
#define OFF_B     67584u         // 128*264*2
#define OFF_TAB   88064u         // + 2*128*40*2
#define SMEM_BYTES 96384u        // + 8*260*4

template <int NMAT>
__global__ void __launch_bounds__(256, 2) hgemm_kernel(
        const float* __restrict__ A,
        const float* __restrict__ W0, const float* __restrict__ W1,
        const float* __restrict__ W2, const float* __restrict__ bias,
        float* __restrict__ C0, float* __restrict__ C1, float* __restrict__ C2) {
    extern __shared__ char smc[];
    __half* Ah = (__half*)smc;
    __half* Bh = (__half*)(smc + OFF_B);
    float* tabsm = (float*)(smc + OFF_TAB);
    uint32_t smb = smem_u32(smc);

    int tid = threadIdx.x, lane = tid & 31, warp = tid >> 5;
    int wm = (warp & 1) * 64;
    int wn = (warp >> 1) * 32;
    long mBase = (long)blockIdx.x * 128;
    int nb = blockIdx.y * 128;
    int gyb = (int)((mBase >> 7) & 7);

    // ---- stage A (fp32 -> fp16), 128 x 256 ----
#pragma unroll
    for (int i = 0; i < 32; i++) {
        int f = tid + i * 256;              // 0..8191
        int row = f >> 6;
        int c4 = (f & 63) << 2;
        float4 v = *(const float4*)(A + (mBase + row) * 256 + c4);
        __half2 h0 = __floats2half2_rn(v.x, v.y);
        __half2 h1 = __floats2half2_rn(v.z, v.w);
        uint2 u = make_uint2(*(uint32_t*)&h0, *(uint32_t*)&h1);
        *(uint2*)(Ah + row * AH_STRIDE + c4) = u;
    }

    // ldmatrix lane addressing pieces
    int lr = lane & 15;
    int lc8 = (lane >> 4) << 3;

    for (int m = 0; m < NMAT; m++) {
        const float* W = (NMAT == 1) ? W0 : (m == 0 ? W0 : (m == 1 ? W1 : W2));
        float* C = (NMAT == 1) ? C0 : (m == 0 ? C0 : (m == 1 ? C1 : C2));
        const float* Wn = W + (size_t)nb * 256;

        float acc[4][4][4];
#pragma unroll
        for (int a = 0; a < 4; a++)
#pragma unroll
            for (int b = 0; b < 4; b++)
#pragma unroll
                for (int r = 0; r < 4; r++) acc[a][b][r] = 0.f;

        // stage B chunk 0 into buf 0
#pragma unroll
        for (int i = 0; i < 4; i++) {
            int f = tid + i * 256;          // 0..1023
            int row = f >> 3;
            int kq = (f & 7) << 2;
            float4 v = *(const float4*)(Wn + (size_t)row * 256 + kq);
            __half2 h0 = __floats2half2_rn(v.x, v.y);
            __half2 h1 = __floats2half2_rn(v.z, v.w);
            uint2 u = make_uint2(*(uint32_t*)&h0, *(uint32_t*)&h1);
            *(uint2*)(Bh + row * BH_STRIDE + kq) = u;
        }
        __syncthreads();

        for (int c = 0; c < 8; c++) {
            int buf = c & 1;
            float4 breg[4];
            if (c < 7) {
                int k0 = (c + 1) * 32;
#pragma unroll
                for (int i = 0; i < 4; i++) {
                    int f = tid + i * 256;
                    int row = f >> 3;
                    int kq = (f & 7) << 2;
                    breg[i] = *(const float4*)(Wn + (size_t)row * 256 + k0 + kq);
                }
            }

            // ---- compute chunk c ----
            uint32_t bB = smb + OFF_B + (uint32_t)buf * (128 * BH_STRIDE * 2);
#pragma unroll
            for (int kt = 0; kt < 2; kt++) {
                int kcol = c * 32 + kt * 16 + lc8;
                uint32_t af[4][4];
#pragma unroll
                for (int mi = 0; mi < 4; mi++) {
                    uint32_t addr = smb + (uint32_t)(((wm + mi * 16 + lr) * AH_STRIDE + kcol) * 2);
                    ldsm4(af[mi][0], af[mi][1], af[mi][2], af[mi][3], addr);
                }
                uint32_t bf[4][2];
#pragma unroll
                for (int ntp = 0; ntp < 2; ntp++) {
                    uint32_t addr = bB + (uint32_t)(((wn + ntp * 16 + lr) * BH_STRIDE + kt * 16 + lc8) * 2);
                    uint32_t r0, r1, r2, r3;
                    ldsm4(r0, r1, r2, r3, addr);
                    bf[ntp * 2][0] = r0; bf[ntp * 2][1] = r2;
                    bf[ntp * 2 + 1][0] = r1; bf[ntp * 2 + 1][1] = r3;
                }
#pragma unroll
                for (int mi = 0; mi < 4; mi++)
#pragma unroll
                    for (int ni = 0; ni < 4; ni++)
                        mma_f16(acc[mi][ni][0], acc[mi][ni][1], acc[mi][ni][2], acc[mi][ni][3],
                                af[mi][0], af[mi][1], af[mi][2], af[mi][3],
                                bf[ni][0], bf[ni][1]);
            }

            if (c < 7) {
                __syncthreads();
#pragma unroll
                for (int i = 0; i < 4; i++) {
                    int f = tid + i * 256;
                    int row = f >> 3;
                    int kq = (f & 7) << 2;
                    __half2 h0 = __floats2half2_rn(breg[i].x, breg[i].y);
                    __half2 h1 = __floats2half2_rn(breg[i].z, breg[i].w);
                    uint2 u = make_uint2(*(uint32_t*)&h0, *(uint32_t*)&h1);
                    *(uint2*)(Bh + (buf ^ 1) * 128 * BH_STRIDE + row * BH_STRIDE + kq) = u;
                }
                __syncthreads();
            }
        }

        // epilogue table (full 256 cols)
#pragma unroll
        for (int i = 0; i < 8; i++) {
            int idx = tid + i * 256;
            int p = idx >> 8, cc = idx & 255;
            tabsm[p * 260 + cc] = (NMAT == 3) ? g_tab[m][gyb * 8 + p][cc] : __ldg(bias + cc);
        }
        __syncthreads();

        // epilogue: same fragment layout as m16n8 accumulators
#pragma unroll
        for (int mi = 0; mi < 4; mi++) {
            int rl = wm + mi * 16 + (lane >> 2);
            long r0 = mBase + rl;
            int prow = rl & 7;
#pragma unroll
            for (int ni = 0; ni < 4; ni++) {
                int colg = nb + wn + ni * 8 + ((lane & 3) << 1);
                float2 t = *(const float2*)&tabsm[prow * 260 + colg];
                *(float2*)(C + r0 * 256 + colg) =
                    make_float2(acc[mi][ni][0] + t.x, acc[mi][ni][1] + t.y);
                *(float2*)(C + (r0 + 8) * 256 + colg) =
                    make_float2(acc[mi][ni][2] + t.x, acc[mi][ni][3] + t.y);
            }
        }
        __syncthreads();   // B buffers + tab reused by next mat
    }
}

// ---------------------------------------------------------------------------
// Attention: one block per (batch, window, head). 4 warps. tf32 (known-good).
// ---------------------------------------------------------------------------
__global__ void __launch_bounds__(128) attn_kernel() {
    __shared__ float Qs[64][36], Ks[64][36], Vs[64][36];
    __shared__ float Ss[64][68];

    int tid = threadIdx.x, lane = tid & 31, warp = tid >> 5;
    int head = blockIdx.x & 7;
    int win = blockIdx.x >> 3;
    int b = win >> 8;
    int wl = win & 255;
    int wyi = wl >> 4, wxi = wl & 15;
    long base = (long)b * 16384;

#pragma unroll
    for (int i = 0; i < 4; i++) {
        int idx = tid + i * 128;
        int p = idx >> 3;
        int cs = (idx & 7) << 2;
        int gy = wyi * 8 + (p >> 3);
        int gx = wxi * 8 + (p & 7);
        long off = (base + gy * 128 + gx) * 256 + head * 32 + cs;
        *(float4*)(&Qs[p][cs]) = *(const float4*)(g_Q + off);
        *(float4*)(&Ks[p][cs]) = *(const float4*)(g_K + off);
        *(float4*)(&Vs[p][cs]) = *(const float4*)(g_V + off);
    }
    __syncthreads();

    float sc[8][4];
#pragma unroll
    for (int nf = 0; nf < 8; nf++)
#pragma unroll
        for (int r = 0; r < 4; r++) sc[nf][r] = 0.f;

#pragma unroll
    for (int kk = 0; kk < 32; kk += 8) {
        int r0 = 16 * warp + (lane >> 2);
        int cA = kk + (lane & 3);
        uint32_t a0 = f2tf(Qs[r0][cA]);
        uint32_t a1 = f2tf(Qs[r0 + 8][cA]);
        uint32_t a2 = f2tf(Qs[r0][cA + 4]);
        uint32_t a3 = f2tf(Qs[r0 + 8][cA + 4]);
#pragma unroll
        for (int nf = 0; nf < 8; nf++) {
            int n = nf * 8 + (lane >> 2);
            uint32_t b0 = f2tf(Ks[n][cA]);
            uint32_t b1 = f2tf(Ks[n][cA + 4]);
            mma_tf32(sc[nf][0], sc[nf][1], sc[nf][2], sc[nf][3], a0, a1, a2, a3, b0, b1);
        }
    }

    const float scale = 0.17677669529663687f;
    float m0 = -1e30f, m1 = -1e30f;
#pragma unroll
    for (int nf = 0; nf < 8; nf++) {
        m0 = fmaxf(m0, fmaxf(sc[nf][0], sc[nf][1]));
        m1 = fmaxf(m1, fmaxf(sc[nf][2], sc[nf][3]));
    }
    m0 = fmaxf(m0, __shfl_xor_sync(0xffffffffu, m0, 1));
    m0 = fmaxf(m0, __shfl_xor_sync(0xffffffffu, m0, 2));
    m1 = fmaxf(m1, __shfl_xor_sync(0xffffffffu, m1, 1));
    m1 = fmaxf(m1, __shfl_xor_sync(0xffffffffu, m1, 2));

    float s0 = 0.f, s1 = 0.f;
#pragma unroll
    for (int nf = 0; nf < 8; nf++) {
        sc[nf][0] = __expf(scale * (sc[nf][0] - m0));
        sc[nf][1] = __expf(scale * (sc[nf][1] - m0));
        sc[nf][2] = __expf(scale * (sc[nf][2] - m1));
        sc[nf][3] = __expf(scale * (sc[nf][3] - m1));
        s0 += sc[nf][0] + sc[nf][1];
        s1 += sc[nf][2] + sc[nf][3];
    }
    s0 += __shfl_xor_sync(0xffffffffu, s0, 1);
    s0 += __shfl_xor_sync(0xffffffffu, s0, 2);
    s1 += __shfl_xor_sync(0xffffffffu, s1, 1);
    s1 += __shfl_xor_sync(0xffffffffu, s1, 2);
    float inv0 = 1.0f / s0, inv1 = 1.0f / s1;

    {
        int r0 = 16 * warp + (lane >> 2);
        int r1 = r0 + 8;
#pragma unroll
        for (int nf = 0; nf < 8; nf++) {
            int c = nf * 8 + ((lane & 3) << 1);
            Ss[r0][c] = sc[nf][0] * inv0;
            Ss[r0][c + 1] = sc[nf][1] * inv0;
            Ss[r1][c] = sc[nf][2] * inv1;
            Ss[r1][c + 1] = sc[nf][3] * inv1;
        }
    }
    __syncwarp();

    float oc[4][4];
#pragma unroll
    for (int nf = 0; nf < 4; nf++)
#pragma unroll
        for (int r = 0; r < 4; r++) oc[nf][r] = 0.f;

#pragma unroll
    for (int kk = 0; kk < 64; kk += 8) {
        int ra = 16 * warp + (lane >> 2);
        int cA = kk + (lane & 3);
        uint32_t a0 = f2tf(Ss[ra][cA]);
        uint32_t a1 = f2tf(Ss[ra + 8][cA]);
        uint32_t a2 = f2tf(Ss[ra][cA + 4]);
        uint32_t a3 = f2tf(Ss[ra + 8][cA + 4]);
#pragma unroll
        for (int nf = 0; nf < 4; nf++) {
            int n = nf * 8 + (lane >> 2);
            uint32_t b0 = f2tf(Vs[kk + (lane & 3)][n]);
            uint32_t b1 = f2tf(Vs[kk + (lane & 3) + 4][n]);
            mma_tf32(oc[nf][0], oc[nf][1], oc[nf][2], oc[nf][3], a0, a1, a2, a3, b0, b1);
        }
    }

    {
        int p0 = 16 * warp + (lane >> 2);
        int p1 = p0 + 8;
        int gy0 = wyi * 8 + (p0 >> 3), gx0 = wxi * 8 + (p0 & 7);
        int gy1 = wyi * 8 + (p1 >> 3), gx1 = wxi * 8 + (p1 & 7);
        long row0 = base + gy0 * 128 + gx0;
        long row1 = base + gy1 * 128 + gx1;
#pragma unroll
        for (int nf = 0; nf < 4; nf++) {
            int col = head * 32 + nf * 8 + ((lane & 3) << 1);
            *(float2*)(g_O + row0 * 256 + col) = make_float2(oc[nf][0], oc[nf][1]);
            *(float2*)(g_O + row1 * 256 + col) = make_float2(oc[nf][2], oc[nf][3]);
        }
    }
}

// ---------------------------------------------------------------------------
// Launch
// ---------------------------------------------------------------------------
extern "C" void kernel_launch(void* const* d_in, const int* in_sizes, int n_in,
                              void* d_out, int out_size) {
    const float* x  = (const float*)d_in[0];
    const float* Wq = (const float*)d_in[1];
    const float* bq = (const float*)d_in[2];
    const float* Wk = (const float*)d_in[3];
    const float* bk = (const float*)d_in[4];
    const float* Wv = (const float*)d_in[5];
    const float* bv = (const float*)d_in[6];
    const float* Wp = (const float*)d_in[7];
    const float* bp = (const float*)d_in[8];
    float* out = (float*)d_out;

    float *Q, *K, *V, *O;
    cudaGetSymbolAddress((void**)&Q, g_Q);
    cudaGetSymbolAddress((void**)&K, g_K);
    cudaGetSymbolAddress((void**)&V, g_V);
    cudaGetSymbolAddress((void**)&O, g_O);

    cudaFuncSetAttribute(hgemm_kernel<3>, cudaFuncAttributeMaxDynamicSharedMemorySize, SMEM_BYTES);
    cudaFuncSetAttribute(hgemm_kernel<1>, cudaFuncAttributeMaxDynamicSharedMemorySize, SMEM_BYTES);

    prep_kernel<<<64, 256>>>(Wq, bq, Wk, bk, bv);

    hgemm_kernel<3><<<dim3(NTOK / 128, 2), 256, SMEM_BYTES>>>(x, Wq, Wk, Wv, nullptr, Q, K, V);

    attn_kernel<<<2048 * NHEAD, 128>>>();

    hgemm_kernel<1><<<dim3(NTOK / 128, 2), 256, SMEM_BYTES>>>(O, Wp, nullptr, nullptr, bp,
                                                              out, nullptr, nullptr);
}

// round 6
// speedup vs baseline: 1.4969x; 1.1153x over previous
#include <cuda_runtime.h>
#include <cuda_fp16.h>
#include <cstdint>

// Fixed shapes: B=8, H=W=128, C=256, heads=8, hd=32, ws=8
#define NTOK  131072
#define NHEAD 8

// Scratch (allocation-free rule: device globals)
__device__ __half g_Qh[(size_t)NTOK * 256];
__device__ __half g_Kh[(size_t)NTOK * 256];
__device__ __half g_Vh[(size_t)NTOK * 256];
__device__ __half g_Oh[(size_t)NTOK * 256];
__device__ float  g_tab[3][64][256];   // q/k: pe@W^T + b ; v: bias

// ---------------------------------------------------------------------------
// helpers
// ---------------------------------------------------------------------------
__device__ __forceinline__ void mma_f16(float& c0, float& c1, float& c2, float& c3,
                                        uint32_t a0, uint32_t a1, uint32_t a2, uint32_t a3,
                                        uint32_t b0, uint32_t b1) {
    asm volatile(
        "mma.sync.aligned.m16n8k16.row.col.f32.f16.f16.f32 "
        "{%0,%1,%2,%3}, {%4,%5,%6,%7}, {%8,%9}, {%0,%1,%2,%3};\n"
        : "+f"(c0), "+f"(c1), "+f"(c2), "+f"(c3)
        : "r"(a0), "r"(a1), "r"(a2), "r"(a3), "r"(b0), "r"(b1));
}

__device__ __forceinline__ void ldsm4(uint32_t& r0, uint32_t& r1, uint32_t& r2, uint32_t& r3,
                                      uint32_t addr) {
    asm volatile("ldmatrix.sync.aligned.m8n8.x4.shared.b16 {%0,%1,%2,%3}, [%4];"
                 : "=r"(r0), "=r"(r1), "=r"(r2), "=r"(r3) : "r"(addr));
}

__device__ __forceinline__ uint32_t smem_u32(const void* p) {
    uint32_t a;
    asm("{ .reg .u64 t; cvta.to.shared.u64 t, %1; cvt.u32.u64 %0, t; }" : "=r"(a) : "l"(p));
    return a;
}

__device__ __forceinline__ uint32_t pack_h2(float lo, float hi) {
    __half2 h = __floats2half2_rn(lo, hi);
    return *(uint32_t*)&h;
}

// ---------------------------------------------------------------------------
// prep: g_tab[0] = pe@Wq^T+bq, g_tab[1] = pe@Wk^T+bk, g_tab[2] = bv
// ---------------------------------------------------------------------------
__global__ void prep_kernel(const float* __restrict__ Wq, const float* __restrict__ bq,
                            const float* __restrict__ Wk, const float* __restrict__ bk,
                            const float* __restrict__ bv) {
    __shared__ float per[256];
    int p = blockIdx.x, n = threadIdx.x;
    int wy = p >> 3, wx = p & 7;
    {
        int f = n & 63, quad = n >> 6;
        float coord = (quad < 2) ? (float)wx : (float)wy;
        float arg = 3.14f * coord * (float)f * (1.0f / 200.0f);
        per[n] = (quad & 1) ? cosf(arg) : sinf(arg);
    }
    __syncthreads();
    float sq = bq[n], sk = bk[n];
    const float* wq = Wq + (size_t)n * 256;
    const float* wk = Wk + (size_t)n * 256;
#pragma unroll 8
    for (int k = 0; k < 256; k++) {
        float pv = per[k];
        sq = fmaf(pv, wq[k], sq);
        sk = fmaf(pv, wk[k], sk);
    }
    g_tab[0][p][n] = sq;
    g_tab[1][p][n] = sk;
    g_tab[2][p][n] = bv[n];
}

// ---------------------------------------------------------------------------
// fp16 GEMM, full-N tile.  Block: 128 M-rows x 256 N-cols, 512 threads
// (16 warps as 2M x 8N, each warp 64x32 via 4x4 m16n8k16 frags).
// A staged ONCE per block into smem fp16 [128][264]; B double-buffered
// [2][256][40] per 32-k chunk (register-staged LDG).
// NMAT=3 (AHALF=0): x fp32 in -> Q,K,V fp16 out, epilogue += g_tab[m].
// NMAT=1 (AHALF=1): O fp16 in -> out fp32, epilogue += bias.
// ---------------------------------------------------------------------------
#define AH_STRIDE 264
#define BH_STRIDE 40
#define OFF_B     67584u                  // 128*264*2
#define OFF_TAB   108544u                 // + 2*256*40*2
#define SMEM_BYTES 116864u                // + 8*260*4

template <int NMAT, int AHALF>
__global__ void __launch_bounds__(512, 1) hgemm_kernel(
        const void* __restrict__ Ain,
        const float* __restrict__ W0, const float* __restrict__ W1,
        const float* __restrict__ W2, const float* __restrict__ bias,
        void* __restrict__ C0v, void* __restrict__ C1v, void* __restrict__ C2v) {
    extern __shared__ char smc[];
    __half* Ah = (__half*)smc;
    __half* Bh = (__half*)(smc + OFF_B);
    float* tabsm = (float*)(smc + OFF_TAB);
    uint32_t smb = smem_u32(smc);

    int tid = threadIdx.x, lane = tid & 31, warp = tid >> 5;
    int wm = (warp & 1) * 64;
    int wn = (warp >> 1) * 32;
    long mBase = (long)blockIdx.x * 128;
    int gyb = (int)((mBase >> 7) & 7);

    // ---- stage A once ----
    if (AHALF) {
        const __half* Af = (const __half*)Ain;
#pragma unroll
        for (int i = 0; i < 8; i++) {
            int f = tid + i * 512;          // 0..4095
            int row = f >> 5;
            int c8 = (f & 31) << 3;
            *(uint4*)(Ah + row * AH_STRIDE + c8) =
                *(const uint4*)(Af + (mBase + row) * 256 + c8);
        }
    } else {
        const float* Af = (const float*)Ain;
#pragma unroll
        for (int i = 0; i < 16; i++) {
            int f = tid + i * 512;          // 0..8191
            int row = f >> 6;
            int c4 = (f & 63) << 2;
            float4 v = *(const float4*)(Af + (mBase + row) * 256 + c4);
            __half2 h0 = __floats2half2_rn(v.x, v.y);
            __half2 h1 = __floats2half2_rn(v.z, v.w);
            *(uint2*)(Ah + row * AH_STRIDE + c4) = make_uint2(*(uint32_t*)&h0, *(uint32_t*)&h1);
        }
    }

    int lr = lane & 15;
    int lc8 = (lane >> 4) << 3;

    for (int m = 0; m < NMAT; m++) {
        const float* W = (NMAT == 1) ? W0 : (m == 0 ? W0 : (m == 1 ? W1 : W2));
        void* Cv = (NMAT == 1) ? C0v : (m == 0 ? C0v : (m == 1 ? C1v : C2v));

        float acc[4][4][4];
#pragma unroll
        for (int a = 0; a < 4; a++)
#pragma unroll
            for (int b = 0; b < 4; b++)
#pragma unroll
                for (int r = 0; r < 4; r++) acc[a][b][r] = 0.f;

        // stage B chunk 0 into buf 0 (256 rows x 32 k)
#pragma unroll
        for (int i = 0; i < 4; i++) {
            int f = tid + i * 512;          // 0..2047
            int row = f >> 3;
            int kq = (f & 7) << 2;
            float4 v = *(const float4*)(W + (size_t)row * 256 + kq);
            __half2 h0 = __floats2half2_rn(v.x, v.y);
            __half2 h1 = __floats2half2_rn(v.z, v.w);
            *(uint2*)(Bh + row * BH_STRIDE + kq) = make_uint2(*(uint32_t*)&h0, *(uint32_t*)&h1);
        }
        __syncthreads();

        for (int c = 0; c < 8; c++) {
            int buf = c & 1;
            float4 breg[4];
            if (c < 7) {
                int k0 = (c + 1) * 32;
#pragma unroll
                for (int i = 0; i < 4; i++) {
                    int f = tid + i * 512;
                    int row = f >> 3;
                    int kq = (f & 7) << 2;
                    breg[i] = *(const float4*)(W + (size_t)row * 256 + k0 + kq);
                }
            }

            uint32_t bB = smb + OFF_B + (uint32_t)buf * (256 * BH_STRIDE * 2);
#pragma unroll
            for (int kt = 0; kt < 2; kt++) {
                int kcol = c * 32 + kt * 16 + lc8;
                uint32_t af[4][4];
#pragma unroll
                for (int mi = 0; mi < 4; mi++) {
                    uint32_t addr = smb + (uint32_t)(((wm + mi * 16 + lr) * AH_STRIDE + kcol) * 2);
                    ldsm4(af[mi][0], af[mi][1], af[mi][2], af[mi][3], addr);
                }
                uint32_t bf[4][2];
#pragma unroll
                for (int ntp = 0; ntp < 2; ntp++) {
                    uint32_t addr = bB + (uint32_t)(((wn + ntp * 16 + lr) * BH_STRIDE + kt * 16 + lc8) * 2);
                    uint32_t r0, r1, r2, r3;
                    ldsm4(r0, r1, r2, r3, addr);
                    bf[ntp * 2][0] = r0; bf[ntp * 2][1] = r2;
                    bf[ntp * 2 + 1][0] = r1; bf[ntp * 2 + 1][1] = r3;
                }
#pragma unroll
                for (int mi = 0; mi < 4; mi++)
#pragma unroll
                    for (int ni = 0; ni < 4; ni++)
                        mma_f16(acc[mi][ni][0], acc[mi][ni][1], acc[mi][ni][2], acc[mi][ni][3],
                                af[mi][0], af[mi][1], af[mi][2], af[mi][3],
                                bf[ni][0], bf[ni][1]);
            }

            if (c < 7) {
                __syncthreads();
#pragma unroll
                for (int i = 0; i < 4; i++) {
                    int f = tid + i * 512;
                    int row = f >> 3;
                    int kq = (f & 7) << 2;
                    __half2 h0 = __floats2half2_rn(breg[i].x, breg[i].y);
                    __half2 h1 = __floats2half2_rn(breg[i].z, breg[i].w);
                    *(uint2*)(Bh + (buf ^ 1) * 256 * BH_STRIDE + row * BH_STRIDE + kq) =
                        make_uint2(*(uint32_t*)&h0, *(uint32_t*)&h1);
                }
                __syncthreads();
            }
        }

        // epilogue table (8 window-x positions x 256 cols)
#pragma unroll
        for (int i = 0; i < 4; i++) {
            int idx = tid + i * 512;        // 0..2047
            int p = idx >> 8, cc = idx & 255;
            tabsm[p * 260 + cc] = (NMAT == 3) ? g_tab[m][gyb * 8 + p][cc] : __ldg(bias + cc);
        }
        __syncthreads();

#pragma unroll
        for (int mi = 0; mi < 4; mi++) {
            int rl = wm + mi * 16 + (lane >> 2);
            long r0 = mBase + rl;
            int prow = rl & 7;
#pragma unroll
            for (int ni = 0; ni < 4; ni++) {
                int colg = wn + ni * 8 + ((lane & 3) << 1);
                float2 t = *(const float2*)&tabsm[prow * 260 + colg];
                if (NMAT == 3) {
                    __half* C = (__half*)Cv;
                    *(uint32_t*)(C + r0 * 256 + colg) =
                        pack_h2(acc[mi][ni][0] + t.x, acc[mi][ni][1] + t.y);
                    *(uint32_t*)(C + (r0 + 8) * 256 + colg) =
                        pack_h2(acc[mi][ni][2] + t.x, acc[mi][ni][3] + t.y);
                } else {
                    float* C = (float*)Cv;
                    *(float2*)(C + r0 * 256 + colg) =
                        make_float2(acc[mi][ni][0] + t.x, acc[mi][ni][1] + t.y);
                    *(float2*)(C + (r0 + 8) * 256 + colg) =
                        make_float2(acc[mi][ni][2] + t.x, acc[mi][ni][3] + t.y);
                }
            }
        }
        __syncthreads();   // B buffers + tab reused by next mat
    }
}

// ---------------------------------------------------------------------------
// Attention, fp16 mma.m16n8k16.  One block per (batch, window, head), 4 warps.
// Fragments assembled as aligned uint32 (half2) LDS — no cvt, no ldmatrix.
// ---------------------------------------------------------------------------
__global__ void __launch_bounds__(128) attn_kernel() {
    __shared__ __half Qs[64][40], Ks[64][40], Vt[32][72];
    __shared__ __half Ss[64][72];

    int tid = threadIdx.x, lane = tid & 31, warp = tid >> 5;
    int head = blockIdx.x & 7;
    int win = blockIdx.x >> 3;
    int b = win >> 8;
    int wl = win & 255;
    int wyi = wl >> 4, wxi = wl & 15;
    long base = (long)b * 16384;

    // load Q/K head slices (64 x 32 halves); V transposed into Vt[col][token]
#pragma unroll
    for (int i = 0; i < 2; i++) {
        int idx = tid + i * 128;            // 0..255
        int p = idx >> 2;
        int cs = (idx & 3) << 3;
        int gy = wyi * 8 + (p >> 3);
        int gx = wxi * 8 + (p & 7);
        long off = (base + gy * 128 + gx) * 256 + head * 32 + cs;
        *(uint4*)(&Qs[p][cs]) = *(const uint4*)(g_Qh + off);
        *(uint4*)(&Ks[p][cs]) = *(const uint4*)(g_Kh + off);
        uint4 v = *(const uint4*)(g_Vh + off);
        const __half* vh = (const __half*)&v;
#pragma unroll
        for (int j = 0; j < 8; j++) Vt[cs + j][p] = vh[j];
    }
    __syncthreads();

    int r0 = 16 * warp + (lane >> 2);
    int kb = (lane & 3) << 1;

    // S = Q K^T  (rows r0, r0+8; all 64 cols; K=32 in two k16 steps)
    float sc[8][4];
#pragma unroll
    for (int nf = 0; nf < 8; nf++)
#pragma unroll
        for (int r = 0; r < 4; r++) sc[nf][r] = 0.f;

#pragma unroll
    for (int kk = 0; kk < 32; kk += 16) {
        uint32_t a0 = *(const uint32_t*)&Qs[r0][kk + kb];
        uint32_t a1 = *(const uint32_t*)&Qs[r0 + 8][kk + kb];
        uint32_t a2 = *(const uint32_t*)&Qs[r0][kk + kb + 8];
        uint32_t a3 = *(const uint32_t*)&Qs[r0 + 8][kk + kb + 8];
#pragma unroll
        for (int nf = 0; nf < 8; nf++) {
            int n = nf * 8 + (lane >> 2);
            uint32_t b0 = *(const uint32_t*)&Ks[n][kk + kb];
            uint32_t b1 = *(const uint32_t*)&Ks[n][kk + kb + 8];
            mma_f16(sc[nf][0], sc[nf][1], sc[nf][2], sc[nf][3], a0, a1, a2, a3, b0, b1);
        }
    }

    // softmax (fp32)
    const float scale = 0.17677669529663687f;   // 1/sqrt(32)
    float m0 = -1e30f, m1 = -1e30f;
#pragma unroll
    for (int nf = 0; nf < 8; nf++) {
        m0 = fmaxf(m0, fmaxf(sc[nf][0], sc[nf][1]));
        m1 = fmaxf(m1, fmaxf(sc[nf][2], sc[nf][3]));
    }
    m0 = fmaxf(m0, __shfl_xor_sync(0xffffffffu, m0, 1));
    m0 = fmaxf(m0, __shfl_xor_sync(0xffffffffu, m0, 2));
    m1 = fmaxf(m1, __shfl_xor_sync(0xffffffffu, m1, 1));
    m1 = fmaxf(m1, __shfl_xor_sync(0xffffffffu, m1, 2));

    float s0 = 0.f, s1 = 0.f;
#pragma unroll
    for (int nf = 0; nf < 8; nf++) {
        sc[nf][0] = __expf(scale * (sc[nf][0] - m0));
        sc[nf][1] = __expf(scale * (sc[nf][1] - m0));
        sc[nf][2] = __expf(scale * (sc[nf][2] - m1));
        sc[nf][3] = __expf(scale * (sc[nf][3] - m1));
        s0 += sc[nf][0] + sc[nf][1];
        s1 += sc[nf][2] + sc[nf][3];
    }
    s0 += __shfl_xor_sync(0xffffffffu, s0, 1);
    s0 += __shfl_xor_sync(0xffffffffu, s0, 2);
    s1 += __shfl_xor_sync(0xffffffffu, s1, 1);
    s1 += __shfl_xor_sync(0xffffffffu, s1, 2);
    float inv0 = 1.0f / s0, inv1 = 1.0f / s1;

#pragma unroll
    for (int nf = 0; nf < 8; nf++) {
        int c = nf * 8 + kb;
        *(uint32_t*)&Ss[r0][c]     = pack_h2(sc[nf][0] * inv0, sc[nf][1] * inv0);
        *(uint32_t*)&Ss[r0 + 8][c] = pack_h2(sc[nf][2] * inv1, sc[nf][3] * inv1);
    }
    __syncwarp();   // warp w's P rows produced and consumed by warp w

    // O = P V  (rows r0, r0+8; 32 cols; K=64 in four k16 steps)
    float oc[4][4];
#pragma unroll
    for (int nf = 0; nf < 4; nf++)
#pragma unroll
        for (int r = 0; r < 4; r++) oc[nf][r] = 0.f;

#pragma unroll
    for (int kk = 0; kk < 64; kk += 16) {
        uint32_t a0 = *(const uint32_t*)&Ss[r0][kk + kb];
        uint32_t a1 = *(const uint32_t*)&Ss[r0 + 8][kk + kb];
        uint32_t a2 = *(const uint32_t*)&Ss[r0][kk + kb + 8];
        uint32_t a3 = *(const uint32_t*)&Ss[r0 + 8][kk + kb + 8];
#pragma unroll
        for (int nf = 0; nf < 4; nf++) {
            int n = nf * 8 + (lane >> 2);
            uint32_t b0 = *(const uint32_t*)&Vt[n][kk + kb];
            uint32_t b1 = *(const uint32_t*)&Vt[n][kk + kb + 8];
            mma_f16(oc[nf][0], oc[nf][1], oc[nf][2], oc[nf][3], a0, a1, a2, a3, b0, b1);
        }
    }

    // write O (fp16, token-major)
    {
        int p0 = r0, p1 = r0 + 8;
        int gy0 = wyi * 8 + (p0 >> 3), gx0 = wxi * 8 + (p0 & 7);
        int gy1 = wyi * 8 + (p1 >> 3), gx1 = wxi * 8 + (p1 & 7);
        long row0 = base + gy0 * 128 + gx0;
        long row1 = base + gy1 * 128 + gx1;
#pragma unroll
        for (int nf = 0; nf < 4; nf++) {
            int col = head * 32 + nf * 8 + kb;
            *(uint32_t*)(g_Oh + row0 * 256 + col) = pack_h2(oc[nf][0], oc[nf][1]);
            *(uint32_t*)(g_Oh + row1 * 256 + col) = pack_h2(oc[nf][2], oc[nf][3]);
        }
    }
}

// ---------------------------------------------------------------------------
// Launch
// ---------------------------------------------------------------------------
extern "C" void kernel_launch(void* const* d_in, const int* in_sizes, int n_in,
                              void* d_out, int out_size) {
    const float* x  = (const float*)d_in[0];
    const float* Wq = (const float*)d_in[1];
    const float* bq = (const float*)d_in[2];
    const float* Wk = (const float*)d_in[3];
    const float* bk = (const float*)d_in[4];
    const float* Wv = (const float*)d_in[5];
    const float* bv = (const float*)d_in[6];
    const float* Wp = (const float*)d_in[7];
    const float* bp = (const float*)d_in[8];
    float* out = (float*)d_out;

    __half *Qh, *Kh, *Vh, *Oh;
    cudaGetSymbolAddress((void**)&Qh, g_Qh);
    cudaGetSymbolAddress((void**)&Kh, g_Kh);
    cudaGetSymbolAddress((void**)&Vh, g_Vh);
    cudaGetSymbolAddress((void**)&Oh, g_Oh);

    cudaFuncSetAttribute((const void*)hgemm_kernel<3, 0>,
                         cudaFuncAttributeMaxDynamicSharedMemorySize, SMEM_BYTES);
    cudaFuncSetAttribute((const void*)hgemm_kernel<1, 1>,
                         cudaFuncAttributeMaxDynamicSharedMemorySize, SMEM_BYTES);

    prep_kernel<<<64, 256>>>(Wq, bq, Wk, bk, bv);

    hgemm_kernel<3, 0><<<NTOK / 128, 512, SMEM_BYTES>>>(x, Wq, Wk, Wv, nullptr, Qh, Kh, Vh);

    attn_kernel<<<2048 * NHEAD, 128>>>();

    hgemm_kernel<1, 1><<<NTOK / 128, 512, SMEM_BYTES>>>(Oh, Wp, nullptr, nullptr, bp,
                                                        out, nullptr, nullptr);
}

// round 7
// speedup vs baseline: 1.5873x; 1.0604x over previous
#include <cuda_runtime.h>
#include <cuda_fp16.h>
#include <cstdint>

// Fixed shapes: B=8, H=W=128, C=256, heads=8, hd=32, ws=8
#define NTOK  131072
#define NHEAD 8

// Scratch (allocation-free rule: device globals)
__device__ __half g_Qh[(size_t)NTOK * 256];
__device__ __half g_Kh[(size_t)NTOK * 256];
__device__ __half g_Vh[(size_t)NTOK * 256];
__device__ __half g_Oh[(size_t)NTOK * 256];
__device__ __half g_Wh[4 * 256 * 256];   // fp16 weights: q,k,v,p
__device__ float  g_tab[3][64][256];     // q/k: pe@W^T + b ; v: bias

// ---------------------------------------------------------------------------
// helpers
// ---------------------------------------------------------------------------
__device__ __forceinline__ void mma_f16(float& c0, float& c1, float& c2, float& c3,
                                        uint32_t a0, uint32_t a1, uint32_t a2, uint32_t a3,
                                        uint32_t b0, uint32_t b1) {
    asm volatile(
        "mma.sync.aligned.m16n8k16.row.col.f32.f16.f16.f32 "
        "{%0,%1,%2,%3}, {%4,%5,%6,%7}, {%8,%9}, {%0,%1,%2,%3};\n"
        : "+f"(c0), "+f"(c1), "+f"(c2), "+f"(c3)
        : "r"(a0), "r"(a1), "r"(a2), "r"(a3), "r"(b0), "r"(b1));
}

__device__ __forceinline__ void ldsm4(uint32_t& r0, uint32_t& r1, uint32_t& r2, uint32_t& r3,
                                      uint32_t addr) {
    asm volatile("ldmatrix.sync.aligned.m8n8.x4.shared.b16 {%0,%1,%2,%3}, [%4];"
                 : "=r"(r0), "=r"(r1), "=r"(r2), "=r"(r3) : "r"(addr));
}

__device__ __forceinline__ void ldsm4t(uint32_t& r0, uint32_t& r1, uint32_t& r2, uint32_t& r3,
                                       uint32_t addr) {
    asm volatile("ldmatrix.sync.aligned.m8n8.x4.trans.shared.b16 {%0,%1,%2,%3}, [%4];"
                 : "=r"(r0), "=r"(r1), "=r"(r2), "=r"(r3) : "r"(addr));
}

__device__ __forceinline__ uint32_t smem_u32(const void* p) {
    uint32_t a;
    asm("{ .reg .u64 t; cvta.to.shared.u64 t, %1; cvt.u32.u64 %0, t; }" : "=r"(a) : "l"(p));
    return a;
}

__device__ __forceinline__ uint32_t pack_h2(float lo, float hi) {
    __half2 h = __floats2half2_rn(lo, hi);
    return *(uint32_t*)&h;
}

__device__ __forceinline__ void cp16(uint32_t smem, const void* gmem) {
    asm volatile("cp.async.cg.shared.global [%0], [%1], 16;" :: "r"(smem), "l"(gmem));
}

// ---------------------------------------------------------------------------
// prep: g_tab[0] = pe@Wq^T+bq, g_tab[1] = pe@Wk^T+bk, g_tab[2] = bv
// ---------------------------------------------------------------------------
__global__ void prep_kernel(const float* __restrict__ Wq, const float* __restrict__ bq,
                            const float* __restrict__ Wk, const float* __restrict__ bk,
                            const float* __restrict__ bv) {
    __shared__ float per[256];
    int p = blockIdx.x, n = threadIdx.x;
    int wy = p >> 3, wx = p & 7;
    {
        int f = n & 63, quad = n >> 6;
        float coord = (quad < 2) ? (float)wx : (float)wy;
        float arg = 3.14f * coord * (float)f * (1.0f / 200.0f);
        per[n] = (quad & 1) ? cosf(arg) : sinf(arg);
    }
    __syncthreads();
    float sq = bq[n], sk = bk[n];
    const float* wq = Wq + (size_t)n * 256;
    const float* wk = Wk + (size_t)n * 256;
#pragma unroll 8
    for (int k = 0; k < 256; k++) {
        float pv = per[k];
        sq = fmaf(pv, wq[k], sq);
        sk = fmaf(pv, wk[k], sk);
    }
    g_tab[0][p][n] = sq;
    g_tab[1][p][n] = sk;
    g_tab[2][p][n] = bv[n];
}

// weights fp32 -> fp16 (one-time)
__global__ void w2h_kernel(const float* __restrict__ Wq, const float* __restrict__ Wk,
                           const float* __restrict__ Wv, const float* __restrict__ Wp) {
    int gid = blockIdx.x * 256 + threadIdx.x;       // 0..65535
    int mat = gid >> 14;
    int off = (gid & 16383) << 2;
    const float* W = (mat == 0) ? Wq : (mat == 1) ? Wk : (mat == 2) ? Wv : Wp;
    float4 v = *(const float4*)(W + off);
    __half2 h0 = __floats2half2_rn(v.x, v.y);
    __half2 h1 = __floats2half2_rn(v.z, v.w);
    *(uint2*)(g_Wh + (size_t)mat * 65536 + off) = make_uint2(*(uint32_t*)&h0, *(uint32_t*)&h1);
}

// ---------------------------------------------------------------------------
// fp16 GEMM, full-N tile.  Block: 128 M x 256 N, 512 threads (16 warps 2Mx8N,
// warp 64x32 via 4x4 m16n8k16).  A resident fp16 [128][264]; B fp16 via
// cp.async double-buffered [2][256][72], k-chunk 64, one barrier per chunk.
// NMAT=3 (AHALF=0): x fp32 -> Q,K,V fp16, epilogue += g_tab[m].
// NMAT=1 (AHALF=1): O fp16 -> out fp32, epilogue += bias.
// ---------------------------------------------------------------------------
#define AH_STRIDE 264
#define BH_STRIDE 72
#define OFF_B     67584u                  // 128*264*2
#define OFF_TAB   141312u                 // + 2*256*72*2
#define SMEM_BYTES 149632u                // + 8*260*4

template <int NMAT, int AHALF>
__global__ void __launch_bounds__(512, 1) hgemm_kernel(
        const void* __restrict__ Ain, const __half* __restrict__ Wh,
        const float* __restrict__ bias,
        void* __restrict__ C0v, void* __restrict__ C1v, void* __restrict__ C2v) {
    extern __shared__ char smc[];
    __half* Ah = (__half*)smc;
    float* tabsm = (float*)(smc + OFF_TAB);
    uint32_t smb = smem_u32(smc);

    int tid = threadIdx.x, lane = tid & 31, warp = tid >> 5;
    int wm = (warp & 1) * 64;
    int wn = (warp >> 1) * 32;
    long mBase = (long)blockIdx.x * 128;
    int gyb = (int)((mBase >> 7) & 7);

    int lr = lane & 15;
    int lc8 = (lane >> 4) << 3;

    // proj: A (fp16) via cp.async, own group
    if (AHALF) {
        const __half* Af = (const __half*)Ain;
#pragma unroll
        for (int i = 0; i < 8; i++) {
            int f = tid + i * 512;          // 0..4095
            int row = f >> 5;
            int c8 = (f & 31) << 3;
            cp16(smb + (uint32_t)(row * AH_STRIDE + c8) * 2,
                 Af + (mBase + row) * 256 + c8);
        }
        asm volatile("cp.async.commit_group;");
    }

    for (int m = 0; m < NMAT; m++) {
        const __half* Wm = Wh + (size_t)m * 65536;
        void* Cv = (NMAT == 1) ? C0v : (m == 0 ? C0v : (m == 1 ? C1v : C2v));

        float acc[4][4][4];
#pragma unroll
        for (int a = 0; a < 4; a++)
#pragma unroll
            for (int b = 0; b < 4; b++)
#pragma unroll
                for (int r = 0; r < 4; r++) acc[a][b][r] = 0.f;

        // issue B chunk 0 (k 0..63) into buf 0
        {
#pragma unroll
            for (int i = 0; i < 4; i++) {
                int f = tid + i * 512;      // 0..2047
                int row = f >> 3, seg = f & 7;
                cp16(smb + OFF_B + (uint32_t)(row * BH_STRIDE + seg * 8) * 2,
                     Wm + (size_t)row * 256 + seg * 8);
            }
            asm volatile("cp.async.commit_group;");
        }

        // QKV: stage A (fp32 -> fp16) once, overlapped with cp.async
        if (!AHALF && m == 0) {
            const float* Af = (const float*)Ain;
#pragma unroll
            for (int i = 0; i < 16; i++) {
                int f = tid + i * 512;      // 0..8191
                int row = f >> 6;
                int c4 = (f & 63) << 2;
                float4 v = *(const float4*)(Af + (mBase + row) * 256 + c4);
                __half2 h0 = __floats2half2_rn(v.x, v.y);
                __half2 h1 = __floats2half2_rn(v.z, v.w);
                *(uint2*)(Ah + row * AH_STRIDE + c4) =
                    make_uint2(*(uint32_t*)&h0, *(uint32_t*)&h1);
            }
        }
        asm volatile("cp.async.wait_group 0;");
        __syncthreads();

        for (int c = 0; c < 4; c++) {
            int buf = c & 1;
            if (c < 3) {                    // issue chunk c+1 into buf^1
                int k0 = (c + 1) * 64;
#pragma unroll
                for (int i = 0; i < 4; i++) {
                    int f = tid + i * 512;
                    int row = f >> 3, seg = f & 7;
                    cp16(smb + OFF_B +
                         (uint32_t)((buf ^ 1) * 256 * BH_STRIDE + row * BH_STRIDE + seg * 8) * 2,
                         Wm + (size_t)row * 256 + k0 + seg * 8);
                }
                asm volatile("cp.async.commit_group;");
            }

            uint32_t bB = smb + OFF_B + (uint32_t)buf * (256 * BH_STRIDE * 2);
#pragma unroll
            for (int kt = 0; kt < 4; kt++) {
                int kcol = c * 64 + kt * 16 + lc8;
                uint32_t af[4][4];
#pragma unroll
                for (int mi = 0; mi < 4; mi++) {
                    uint32_t addr = smb + (uint32_t)(((wm + mi * 16 + lr) * AH_STRIDE + kcol) * 2);
                    ldsm4(af[mi][0], af[mi][1], af[mi][2], af[mi][3], addr);
                }
                uint32_t bf[4][2];
#pragma unroll
                for (int ntp = 0; ntp < 2; ntp++) {
                    uint32_t addr = bB +
                        (uint32_t)(((wn + ntp * 16 + lr) * BH_STRIDE + kt * 16 + lc8) * 2);
                    uint32_t r0, r1, r2, r3;
                    ldsm4(r0, r1, r2, r3, addr);
                    bf[ntp * 2][0] = r0; bf[ntp * 2][1] = r2;
                    bf[ntp * 2 + 1][0] = r1; bf[ntp * 2 + 1][1] = r3;
                }
#pragma unroll
                for (int mi = 0; mi < 4; mi++)
#pragma unroll
                    for (int ni = 0; ni < 4; ni++)
                        mma_f16(acc[mi][ni][0], acc[mi][ni][1], acc[mi][ni][2], acc[mi][ni][3],
                                af[mi][0], af[mi][1], af[mi][2], af[mi][3],
                                bf[ni][0], bf[ni][1]);
            }

            if (c < 3) asm volatile("cp.async.wait_group 0;");
            __syncthreads();
        }

        // epilogue table (8 window-x positions x 256 cols)
#pragma unroll
        for (int i = 0; i < 4; i++) {
            int idx = tid + i * 512;
            int p = idx >> 8, cc = idx & 255;
            tabsm[p * 260 + cc] = (NMAT == 3) ? g_tab[m][gyb * 8 + p][cc] : __ldg(bias + cc);
        }
        __syncthreads();

#pragma unroll
        for (int mi = 0; mi < 4; mi++) {
            int rl = wm + mi * 16 + (lane >> 2);
            long r0 = mBase + rl;
            int prow = rl & 7;
#pragma unroll
            for (int ni = 0; ni < 4; ni++) {
                int colg = wn + ni * 8 + ((lane & 3) << 1);
                float2 t = *(const float2*)&tabsm[prow * 260 + colg];
                if (NMAT == 3) {
                    __half* C = (__half*)Cv;
                    *(uint32_t*)(C + r0 * 256 + colg) =
                        pack_h2(acc[mi][ni][0] + t.x, acc[mi][ni][1] + t.y);
                    *(uint32_t*)(C + (r0 + 8) * 256 + colg) =
                        pack_h2(acc[mi][ni][2] + t.x, acc[mi][ni][3] + t.y);
                } else {
                    float* C = (float*)Cv;
                    *(float2*)(C + r0 * 256 + colg) =
                        make_float2(acc[mi][ni][0] + t.x, acc[mi][ni][1] + t.y);
                    *(float2*)(C + (r0 + 8) * 256 + colg) =
                        make_float2(acc[mi][ni][2] + t.x, acc[mi][ni][3] + t.y);
                }
            }
        }
        __syncthreads();   // tab + B buffers reused by next mat
    }
}

// ---------------------------------------------------------------------------
// Attention, fp16 mma.m16n8k16 with ldmatrix fragment feeds.
// One block per (batch, window, head), 4 warps.
// V kept row-major; PV B-frags via ldmatrix.trans (no scalar transpose).
// ---------------------------------------------------------------------------
__global__ void __launch_bounds__(128) attn_kernel() {
    __shared__ __half Qs[64][40], Ks[64][40], Vs[64][40];
    __shared__ __half Ss[64][72];

    int tid = threadIdx.x, lane = tid & 31, warp = tid >> 5;
    int head = blockIdx.x & 7;
    int win = blockIdx.x >> 3;
    int b = win >> 8;
    int wl = win & 255;
    int wyi = wl >> 4, wxi = wl & 15;
    long base = (long)b * 16384;

    // load Q/K/V head slices (64 x 32 halves, uint4)
#pragma unroll
    for (int i = 0; i < 2; i++) {
        int idx = tid + i * 128;            // 0..255
        int p = idx >> 2;
        int cs = (idx & 3) << 3;
        int gy = wyi * 8 + (p >> 3);
        int gx = wxi * 8 + (p & 7);
        long off = (base + gy * 128 + gx) * 256 + head * 32 + cs;
        *(uint4*)(&Qs[p][cs]) = *(const uint4*)(g_Qh + off);
        *(uint4*)(&Ks[p][cs]) = *(const uint4*)(g_Kh + off);
        *(uint4*)(&Vs[p][cs]) = *(const uint4*)(g_Vh + off);
    }
    __syncthreads();

    int r0b = 16 * warp;
    int r0 = r0b + (lane >> 2);
    int kb = (lane & 3) << 1;
    int lr = lane & 15;
    int lc8 = (lane >> 4) << 3;

    // S = Q K^T
    float sc[8][4];
#pragma unroll
    for (int nf = 0; nf < 8; nf++)
#pragma unroll
        for (int r = 0; r < 4; r++) sc[nf][r] = 0.f;

#pragma unroll
    for (int kk = 0; kk < 32; kk += 16) {
        uint32_t a0, a1, a2, a3;
        ldsm4(a0, a1, a2, a3, smem_u32(&Qs[r0b + lr][kk + lc8]));
#pragma unroll
        for (int nt = 0; nt < 4; nt++) {
            uint32_t b0, b1, b2, b3;
            ldsm4(b0, b1, b2, b3, smem_u32(&Ks[nt * 16 + lr][kk + lc8]));
            mma_f16(sc[nt * 2][0], sc[nt * 2][1], sc[nt * 2][2], sc[nt * 2][3],
                    a0, a1, a2, a3, b0, b2);
            mma_f16(sc[nt * 2 + 1][0], sc[nt * 2 + 1][1], sc[nt * 2 + 1][2], sc[nt * 2 + 1][3],
                    a0, a1, a2, a3, b1, b3);
        }
    }

    // softmax (fp32)
    const float scale = 0.17677669529663687f;   // 1/sqrt(32)
    float m0 = -1e30f, m1 = -1e30f;
#pragma unroll
    for (int nf = 0; nf < 8; nf++) {
        m0 = fmaxf(m0, fmaxf(sc[nf][0], sc[nf][1]));
        m1 = fmaxf(m1, fmaxf(sc[nf][2], sc[nf][3]));
    }
    m0 = fmaxf(m0, __shfl_xor_sync(0xffffffffu, m0, 1));
    m0 = fmaxf(m0, __shfl_xor_sync(0xffffffffu, m0, 2));
    m1 = fmaxf(m1, __shfl_xor_sync(0xffffffffu, m1, 1));
    m1 = fmaxf(m1, __shfl_xor_sync(0xffffffffu, m1, 2));

    float s0 = 0.f, s1 = 0.f;
#pragma unroll
    for (int nf = 0; nf < 8; nf++) {
        sc[nf][0] = __expf(scale * (sc[nf][0] - m0));
        sc[nf][1] = __expf(scale * (sc[nf][1] - m0));
        sc[nf][2] = __expf(scale * (sc[nf][2] - m1));
        sc[nf][3] = __expf(scale * (sc[nf][3] - m1));
        s0 += sc[nf][0] + sc[nf][1];
        s1 += sc[nf][2] + sc[nf][3];
    }
    s0 += __shfl_xor_sync(0xffffffffu, s0, 1);
    s0 += __shfl_xor_sync(0xffffffffu, s0, 2);
    s1 += __shfl_xor_sync(0xffffffffu, s1, 1);
    s1 += __shfl_xor_sync(0xffffffffu, s1, 2);
    float inv0 = 1.0f / s0, inv1 = 1.0f / s1;

#pragma unroll
    for (int nf = 0; nf < 8; nf++) {
        int c = nf * 8 + kb;
        *(uint32_t*)&Ss[r0][c]     = pack_h2(sc[nf][0] * inv0, sc[nf][1] * inv0);
        *(uint32_t*)&Ss[r0 + 8][c] = pack_h2(sc[nf][2] * inv1, sc[nf][3] * inv1);
    }
    __syncwarp();   // warp's P rows produced and consumed by itself

    // O = P V   (B-frags from row-major V via ldmatrix.trans)
    float oc[4][4];
#pragma unroll
    for (int nf = 0; nf < 4; nf++)
#pragma unroll
        for (int r = 0; r < 4; r++) oc[nf][r] = 0.f;

#pragma unroll
    for (int kk = 0; kk < 64; kk += 16) {
        uint32_t a0, a1, a2, a3;
        ldsm4(a0, a1, a2, a3, smem_u32(&Ss[r0b + lr][kk + lc8]));
#pragma unroll
        for (int tt = 0; tt < 2; tt++) {
            uint32_t b0, b1, b2, b3;
            ldsm4t(b0, b1, b2, b3, smem_u32(&Vs[kk + lr][tt * 16 + lc8]));
            mma_f16(oc[tt * 2][0], oc[tt * 2][1], oc[tt * 2][2], oc[tt * 2][3],
                    a0, a1, a2, a3, b0, b1);
            mma_f16(oc[tt * 2 + 1][0], oc[tt * 2 + 1][1], oc[tt * 2 + 1][2], oc[tt * 2 + 1][3],
                    a0, a1, a2, a3, b2, b3);
        }
    }

    // write O (fp16, token-major)
    {
        int p0 = r0, p1 = r0 + 8;
        int gy0 = wyi * 8 + (p0 >> 3), gx0 = wxi * 8 + (p0 & 7);
        int gy1 = wyi * 8 + (p1 >> 3), gx1 = wxi * 8 + (p1 & 7);
        long row0 = base + gy0 * 128 + gx0;
        long row1 = base + gy1 * 128 + gx1;
#pragma unroll
        for (int nf = 0; nf < 4; nf++) {
            int col = head * 32 + nf * 8 + kb;
            *(uint32_t*)(g_Oh + row0 * 256 + col) = pack_h2(oc[nf][0], oc[nf][1]);
            *(uint32_t*)(g_Oh + row1 * 256 + col) = pack_h2(oc[nf][2], oc[nf][3]);
        }
    }
}

// ---------------------------------------------------------------------------
// Launch
// ---------------------------------------------------------------------------
extern "C" void kernel_launch(void* const* d_in, const int* in_sizes, int n_in,
                              void* d_out, int out_size) {
    const float* x  = (const float*)d_in[0];
    const float* Wq = (const float*)d_in[1];
    const float* bq = (const float*)d_in[2];
    const float* Wk = (const float*)d_in[3];
    const float* bk = (const float*)d_in[4];
    const float* Wv = (const float*)d_in[5];
    const float* bv = (const float*)d_in[6];
    const float* Wp = (const float*)d_in[7];
    const float* bp = (const float*)d_in[8];
    float* out = (float*)d_out;

    __half *Qh, *Kh, *Vh, *Oh, *Wh;
    cudaGetSymbolAddress((void**)&Qh, g_Qh);
    cudaGetSymbolAddress((void**)&Kh, g_Kh);
    cudaGetSymbolAddress((void**)&Vh, g_Vh);
    cudaGetSymbolAddress((void**)&Oh, g_Oh);
    cudaGetSymbolAddress((void**)&Wh, g_Wh);

    cudaFuncSetAttribute((const void*)hgemm_kernel<3, 0>,
                         cudaFuncAttributeMaxDynamicSharedMemorySize, SMEM_BYTES);
    cudaFuncSetAttribute((const void*)hgemm_kernel<1, 1>,
                         cudaFuncAttributeMaxDynamicSharedMemorySize, SMEM_BYTES);

    prep_kernel<<<64, 256>>>(Wq, bq, Wk, bk, bv);
    w2h_kernel<<<256, 256>>>(Wq, Wk, Wv, Wp);

    hgemm_kernel<3, 0><<<NTOK / 128, 512, SMEM_BYTES>>>(x, Wh, nullptr, Qh, Kh, Vh);

    attn_kernel<<<2048 * NHEAD, 128>>>();

    hgemm_kernel<1, 1><<<NTOK / 128, 512, SMEM_BYTES>>>(Oh, Wh + 3 * 65536, bp,
                                                        out, nullptr, nullptr);
}

// round 9
// speedup vs baseline: 1.8424x; 1.1607x over previous
#include <cuda_runtime.h>
#include <cuda_fp16.h>
#include <cstdint>

// Fixed shapes: B=8, H=W=128, C=256, heads=8, hd=32, ws=8
#define NTOK  131072

// device-global scratch (allocation-free rule)
__device__ __half g_Wh[4 * 256 * 256];        // fp16 weights: q,k,v,p
__device__ __half g_tabh[3][64][256];         // fp16: pe@Wq^T+bq, pe@Wk^T+bk, bv

// ---------------------------------------------------------------------------
// helpers
// ---------------------------------------------------------------------------
__device__ __forceinline__ void mma_f16(float& c0, float& c1, float& c2, float& c3,
                                        uint32_t a0, uint32_t a1, uint32_t a2, uint32_t a3,
                                        uint32_t b0, uint32_t b1) {
    asm volatile(
        "mma.sync.aligned.m16n8k16.row.col.f32.f16.f16.f32 "
        "{%0,%1,%2,%3}, {%4,%5,%6,%7}, {%8,%9}, {%0,%1,%2,%3};\n"
        : "+f"(c0), "+f"(c1), "+f"(c2), "+f"(c3)
        : "r"(a0), "r"(a1), "r"(a2), "r"(a3), "r"(b0), "r"(b1));
}

__device__ __forceinline__ void ldsm4(uint32_t& r0, uint32_t& r1, uint32_t& r2, uint32_t& r3,
                                      uint32_t addr) {
    asm volatile("ldmatrix.sync.aligned.m8n8.x4.shared.b16 {%0,%1,%2,%3}, [%4];"
                 : "=r"(r0), "=r"(r1), "=r"(r2), "=r"(r3) : "r"(addr));
}

__device__ __forceinline__ void ldsm4t(uint32_t& r0, uint32_t& r1, uint32_t& r2, uint32_t& r3,
                                       uint32_t addr) {
    asm volatile("ldmatrix.sync.aligned.m8n8.x4.trans.shared.b16 {%0,%1,%2,%3}, [%4];"
                 : "=r"(r0), "=r"(r1), "=r"(r2), "=r"(r3) : "r"(addr));
}

__device__ __forceinline__ uint32_t smem_u32(const void* p) {
    uint32_t a;
    asm("{ .reg .u64 t; cvta.to.shared.u64 t, %1; cvt.u32.u64 %0, t; }" : "=r"(a) : "l"(p));
    return a;
}

__device__ __forceinline__ uint32_t pack_h2(float lo, float hi) {
    __half2 h = __floats2half2_rn(lo, hi);
    return *(uint32_t*)&h;
}

__device__ __forceinline__ void cp16(uint32_t smem, const void* gmem) {
    asm volatile("cp.async.cg.shared.global [%0], [%1], 16;" :: "r"(smem), "l"(gmem));
}

// ---------------------------------------------------------------------------
// prep: g_tabh[0] = pe@Wq^T+bq, [1] = pe@Wk^T+bk, [2] = bv  (fp16)
// ---------------------------------------------------------------------------
__global__ void prep_kernel(const float* __restrict__ Wq, const float* __restrict__ bq,
                            const float* __restrict__ Wk, const float* __restrict__ bk,
                            const float* __restrict__ bv) {
    __shared__ float per[256];
    int p = blockIdx.x, n = threadIdx.x;
    int wy = p >> 3, wx = p & 7;
    {
        int f = n & 63, quad = n >> 6;
        float coord = (quad < 2) ? (float)wx : (float)wy;
        float arg = 3.14f * coord * (float)f * (1.0f / 200.0f);
        per[n] = (quad & 1) ? cosf(arg) : sinf(arg);
    }
    __syncthreads();
    float sq = bq[n], sk = bk[n];
    const float* wq = Wq + (size_t)n * 256;
    const float* wk = Wk + (size_t)n * 256;
#pragma unroll 8
    for (int k = 0; k < 256; k++) {
        float pv = per[k];
        sq = fmaf(pv, wq[k], sq);
        sk = fmaf(pv, wk[k], sk);
    }
    g_tabh[0][p][n] = __float2half_rn(sq);
    g_tabh[1][p][n] = __float2half_rn(sk);
    g_tabh[2][p][n] = __float2half_rn(bv[n]);
}

// weights fp32 -> fp16 (one-time); layout [q,k,v,p]
__global__ void w2h_kernel(const float* __restrict__ Wq, const float* __restrict__ Wk,
                           const float* __restrict__ Wv, const float* __restrict__ Wp) {
    int gid = blockIdx.x * 256 + threadIdx.x;       // 0..65535
    int mat = gid >> 14;
    int off = (gid & 16383) << 2;
    const float* W = (mat == 0) ? Wq : (mat == 1) ? Wk : (mat == 2) ? Wv : Wp;
    float4 v = *(const float4*)(W + off);
    __half2 h0 = __floats2half2_rn(v.x, v.y);
    __half2 h1 = __floats2half2_rn(v.z, v.w);
    *(uint2*)(g_Wh + (size_t)mat * 65536 + off) = make_uint2(*(uint32_t*)&h0, *(uint32_t*)&h1);
}

// ---------------------------------------------------------------------------
// Fused kernel: one block per window (64 tokens), 512 threads / 16 warps.
// warp = (mi = warp&1 -> 32 query rows, hn = warp>>1 -> head / 32-col slice).
// Phases: stage x -> GEMM K -> GEMM V -> GEMM Q (regs) -> attention -> O to
// smem -> GEMM proj -> out.  Weights stream via cp.async (L2-resident).
// ---------------------------------------------------------------------------
#define AHS 264                   // halves; row stride of As/Ks/Vs
#define BHS 72                    // halves; weight-chunk row stride
#define OFF_K  33792u             // 64*264*2
#define OFF_V  67584u
#define OFF_B  101376u            // + 64*264*2
#define SMEM_BYTES 175104u        // + 2*256*72*2

__global__ void __launch_bounds__(512, 1) fused_kernel(
        const float* __restrict__ x, const __half* __restrict__ Wh,
        const float* __restrict__ bp, float* __restrict__ out) {
    extern __shared__ char smc[];
    __half* As = (__half*)smc;            // x tile, later O tile
    uint32_t smb = smem_u32(smc);

    int tid = threadIdx.x, lane = tid & 31, warp = tid >> 5;
    int mi = warp & 1, hn = warp >> 1;
    int lr = lane & 15, lc8 = (lane >> 4) << 3;
    int lq = lane >> 2, kb2 = (lane & 3) << 1;

    int win = blockIdx.x;
    int bi = win >> 8, wl = win & 255;
    int wyi = wl >> 4, wxi = wl & 15;
    long base = (long)bi * 16384 + (wyi * 8) * 128 + wxi * 8;   // + (t>>3)*128 + (t&7)

    // ---- stage x window tile (64 x 256 fp32 -> fp16 smem) ----
#pragma unroll
    for (int i = 0; i < 8; i++) {
        int f = tid + i * 512;            // 0..4095
        int t = f >> 6;
        int c4 = (f & 63) << 2;
        long gr = base + (t >> 3) * 128 + (t & 7);
        float4 v = *(const float4*)(x + gr * 256 + c4);
        __half2 h0 = __floats2half2_rn(v.x, v.y);
        __half2 h1 = __floats2half2_rn(v.z, v.w);
        *(uint2*)(As + t * AHS + c4) = make_uint2(*(uint32_t*)&h0, *(uint32_t*)&h1);
    }
    // (ordered by the barrier inside the first run_gemm)

    // ---- shared GEMM mainloop: acc[mf][ni] = A[rows mi*32..] @ Wm[cols hn*32..]^T
    auto run_gemm = [&](const __half* Wm, float (&acc)[2][4][4]) {
#pragma unroll
        for (int a = 0; a < 2; a++)
#pragma unroll
            for (int b = 0; b < 4; b++)
#pragma unroll
                for (int r = 0; r < 4; r++) acc[a][b][r] = 0.f;
        // issue chunk 0 (256 rows x 64 halves = 8 x 16B segs per row)
#pragma unroll
        for (int i = 0; i < 4; i++) {
            int f = tid + i * 512;        // 0..2047
            int row = f >> 3, seg = f & 7;
            cp16(smb + OFF_B + (uint32_t)(row * BHS + seg * 8) * 2,
                 Wm + (size_t)row * 256 + seg * 8);
        }
        asm volatile("cp.async.commit_group;");
        asm volatile("cp.async.wait_group 0;");
        __syncthreads();

        for (int c = 0; c < 4; c++) {
            int buf = c & 1;
            if (c < 3) {
                int k0 = (c + 1) * 64;
#pragma unroll
                for (int i = 0; i < 4; i++) {
                    int f = tid + i * 512;
                    int row = f >> 3, seg = f & 7;
                    cp16(smb + OFF_B +
                         (uint32_t)((buf ^ 1) * 256 * BHS + row * BHS + seg * 8) * 2,
                         Wm + (size_t)row * 256 + k0 + seg * 8);
                }
                asm volatile("cp.async.commit_group;");
            }
            uint32_t bB = smb + OFF_B + (uint32_t)buf * (256 * BHS * 2);
#pragma unroll
            for (int kt = 0; kt < 4; kt++) {
                int kcol = c * 64 + kt * 16 + lc8;
                uint32_t af[2][4];
#pragma unroll
                for (int mf = 0; mf < 2; mf++)
                    ldsm4(af[mf][0], af[mf][1], af[mf][2], af[mf][3],
                          smb + (uint32_t)(((mi * 32 + mf * 16 + lr) * AHS + kcol) * 2));
                uint32_t bf[4][2];
#pragma unroll
                for (int ntp = 0; ntp < 2; ntp++) {
                    uint32_t r0, r1, r2, r3;
                    ldsm4(r0, r1, r2, r3,
                          bB + (uint32_t)(((hn * 32 + ntp * 16 + lr) * BHS + kt * 16 + lc8) * 2));
                    bf[ntp * 2][0] = r0; bf[ntp * 2][1] = r2;
                    bf[ntp * 2 + 1][0] = r1; bf[ntp * 2 + 1][1] = r3;
                }
#pragma unroll
                for (int mf = 0; mf < 2; mf++)
#pragma unroll
                    for (int ni = 0; ni < 4; ni++)
                        mma_f16(acc[mf][ni][0], acc[mf][ni][1], acc[mf][ni][2], acc[mf][ni][3],
                                af[mf][0], af[mf][1], af[mf][2], af[mf][3],
                                bf[ni][0], bf[ni][1]);
            }
            if (c < 3) asm volatile("cp.async.wait_group 0;");
            __syncthreads();
        }
    };

    // C-frag + fp16 table -> smem (used for K and V)
    auto store_kv = [&](float (&acc)[2][4][4], const __half* tab, uint32_t dstOff) {
#pragma unroll
        for (int mf = 0; mf < 2; mf++) {
            int r = mi * 32 + mf * 16 + lq;
#pragma unroll
            for (int ni = 0; ni < 4; ni++) {
                int cb = hn * 32 + ni * 8 + kb2;
                float2 t0 = __half22float2(*(const __half2*)&tab[r * 256 + cb]);
                float2 t1 = __half22float2(*(const __half2*)&tab[(r + 8) * 256 + cb]);
                *(uint32_t*)(smc + dstOff + (uint32_t)((r * AHS + cb) * 2)) =
                    pack_h2(acc[mf][ni][0] + t0.x, acc[mf][ni][1] + t0.y);
                *(uint32_t*)(smc + dstOff + (uint32_t)(((r + 8) * AHS + cb) * 2)) =
                    pack_h2(acc[mf][ni][2] + t1.x, acc[mf][ni][3] + t1.y);
            }
        }
    };

    float acc[2][4][4];

    // ---- K, V ----
    run_gemm(Wh + 65536, acc);                     // Wk
    store_kv(acc, &g_tabh[1][0][0], OFF_K);
    run_gemm(Wh + 131072, acc);                    // Wv
    store_kv(acc, &g_tabh[2][0][0], OFF_V);

    // ---- Q (stays in registers as mma A-frags, scale folded) ----
    run_gemm(Wh, acc);                             // Wq
    uint32_t afQ[2][2][4];
    {
        const __half* tq = &g_tabh[0][0][0];
        const float s = 0.17677669529663687f;      // 1/sqrt(32)
#pragma unroll
        for (int mf = 0; mf < 2; mf++) {
            int r = mi * 32 + mf * 16 + lq;
#pragma unroll
            for (int kf = 0; kf < 2; kf++) {
#pragma unroll
                for (int h = 0; h < 2; h++) {
                    int ni = 2 * kf + h;
                    int cb = hn * 32 + ni * 8 + kb2;
                    float2 t0 = __half22float2(*(const __half2*)&tq[r * 256 + cb]);
                    float2 t1 = __half22float2(*(const __half2*)&tq[(r + 8) * 256 + cb]);
                    afQ[mf][kf][2 * h] =
                        pack_h2((acc[mf][ni][0] + t0.x) * s, (acc[mf][ni][1] + t0.y) * s);
                    afQ[mf][kf][2 * h + 1] =
                        pack_h2((acc[mf][ni][2] + t1.x) * s, (acc[mf][ni][3] + t1.y) * s);
                }
            }
        }
    }

    // ---- S = Q K^T (32 rows x 64 keys per warp) ----
    float sc[2][8][4];
#pragma unroll
    for (int mf = 0; mf < 2; mf++)
#pragma unroll
        for (int nf = 0; nf < 8; nf++)
#pragma unroll
            for (int r = 0; r < 4; r++) sc[mf][nf][r] = 0.f;

#pragma unroll
    for (int kt = 0; kt < 2; kt++) {
#pragma unroll
        for (int nt = 0; nt < 4; nt++) {
            uint32_t b0, b1, b2, b3;
            ldsm4(b0, b1, b2, b3,
                  smb + OFF_K + (uint32_t)(((nt * 16 + lr) * AHS + hn * 32 + kt * 16 + lc8) * 2));
#pragma unroll
            for (int mf = 0; mf < 2; mf++) {
                mma_f16(sc[mf][nt * 2][0], sc[mf][nt * 2][1], sc[mf][nt * 2][2], sc[mf][nt * 2][3],
                        afQ[mf][kt][0], afQ[mf][kt][1], afQ[mf][kt][2], afQ[mf][kt][3], b0, b2);
                mma_f16(sc[mf][nt * 2 + 1][0], sc[mf][nt * 2 + 1][1],
                        sc[mf][nt * 2 + 1][2], sc[mf][nt * 2 + 1][3],
                        afQ[mf][kt][0], afQ[mf][kt][1], afQ[mf][kt][2], afQ[mf][kt][3], b1, b3);
            }
        }
    }

    // ---- softmax + P pack (scale already folded into Q) ----
    uint32_t pa[2][4][4];
#pragma unroll
    for (int mf = 0; mf < 2; mf++) {
        float m0 = -1e30f, m1 = -1e30f;
#pragma unroll
        for (int nf = 0; nf < 8; nf++) {
            m0 = fmaxf(m0, fmaxf(sc[mf][nf][0], sc[mf][nf][1]));
            m1 = fmaxf(m1, fmaxf(sc[mf][nf][2], sc[mf][nf][3]));
        }
        m0 = fmaxf(m0, __shfl_xor_sync(0xffffffffu, m0, 1));
        m0 = fmaxf(m0, __shfl_xor_sync(0xffffffffu, m0, 2));
        m1 = fmaxf(m1, __shfl_xor_sync(0xffffffffu, m1, 1));
        m1 = fmaxf(m1, __shfl_xor_sync(0xffffffffu, m1, 2));
        float s0 = 0.f, s1 = 0.f;
#pragma unroll
        for (int nf = 0; nf < 8; nf++) {
            sc[mf][nf][0] = __expf(sc[mf][nf][0] - m0);
            sc[mf][nf][1] = __expf(sc[mf][nf][1] - m0);
            sc[mf][nf][2] = __expf(sc[mf][nf][2] - m1);
            sc[mf][nf][3] = __expf(sc[mf][nf][3] - m1);
            s0 += sc[mf][nf][0] + sc[mf][nf][1];
            s1 += sc[mf][nf][2] + sc[mf][nf][3];
        }
        s0 += __shfl_xor_sync(0xffffffffu, s0, 1);
        s0 += __shfl_xor_sync(0xffffffffu, s0, 2);
        s1 += __shfl_xor_sync(0xffffffffu, s1, 1);
        s1 += __shfl_xor_sync(0xffffffffu, s1, 2);
        float inv0 = 1.0f / s0, inv1 = 1.0f / s1;
#pragma unroll
        for (int kf = 0; kf < 4; kf++) {
            pa[mf][kf][0] = pack_h2(sc[mf][2 * kf][0] * inv0, sc[mf][2 * kf][1] * inv0);
            pa[mf][kf][1] = pack_h2(sc[mf][2 * kf][2] * inv1, sc[mf][2 * kf][3] * inv1);
            pa[mf][kf][2] = pack_h2(sc[mf][2 * kf + 1][0] * inv0, sc[mf][2 * kf + 1][1] * inv0);
            pa[mf][kf][3] = pack_h2(sc[mf][2 * kf + 1][2] * inv1, sc[mf][2 * kf + 1][3] * inv1);
        }
    }

    // ---- O = P V ----
    float oc[2][4][4];
#pragma unroll
    for (int mf = 0; mf < 2; mf++)
#pragma unroll
        for (int nf = 0; nf < 4; nf++)
#pragma unroll
            for (int r = 0; r < 4; r++) oc[mf][nf][r] = 0.f;

#pragma unroll
    for (int kf = 0; kf < 4; kf++) {
#pragma unroll
        for (int tt = 0; tt < 2; tt++) {
            uint32_t b0, b1, b2, b3;
            ldsm4t(b0, b1, b2, b3,
                   smb + OFF_V + (uint32_t)(((kf * 16 + lr) * AHS + hn * 32 + tt * 16 + lc8) * 2));
#pragma unroll
            for (int mf = 0; mf < 2; mf++) {
                mma_f16(oc[mf][tt * 2][0], oc[mf][tt * 2][1], oc[mf][tt * 2][2], oc[mf][tt * 2][3],
                        pa[mf][kf][0], pa[mf][kf][1], pa[mf][kf][2], pa[mf][kf][3], b0, b1);
                mma_f16(oc[mf][tt * 2 + 1][0], oc[mf][tt * 2 + 1][1],
                        oc[mf][tt * 2 + 1][2], oc[mf][tt * 2 + 1][3],
                        pa[mf][kf][0], pa[mf][kf][1], pa[mf][kf][2], pa[mf][kf][3], b2, b3);
            }
        }
    }

    // ---- store O into the dead x-tile buffer ----
#pragma unroll
    for (int mf = 0; mf < 2; mf++) {
        int r = mi * 32 + mf * 16 + lq;
#pragma unroll
        for (int ni = 0; ni < 4; ni++) {
            int cb = hn * 32 + ni * 8 + kb2;
            *(uint32_t*)(As + r * AHS + cb) = pack_h2(oc[mf][ni][0], oc[mf][ni][1]);
            *(uint32_t*)(As + (r + 8) * AHS + cb) = pack_h2(oc[mf][ni][2], oc[mf][ni][3]);
        }
    }

    // ---- projection: out = O @ Wp^T + bp (barrier inside run_gemm orders O stores) ----
    run_gemm(Wh + 196608, acc);                    // Wp
#pragma unroll
    for (int mf = 0; mf < 2; mf++) {
        int r = mi * 32 + mf * 16 + lq;
        long gr0 = base + (r >> 3) * 128 + (r & 7);
        long gr1 = base + ((r + 8) >> 3) * 128 + ((r + 8) & 7);
#pragma unroll
        for (int ni = 0; ni < 4; ni++) {
            int cb = hn * 32 + ni * 8 + kb2;
            float b0 = __ldg(bp + cb), b1 = __ldg(bp + cb + 1);
            *(float2*)(out + gr0 * 256 + cb) =
                make_float2(acc[mf][ni][0] + b0, acc[mf][ni][1] + b1);
            *(float2*)(out + gr1 * 256 + cb) =
                make_float2(acc[mf][ni][2] + b0, acc[mf][ni][3] + b1);
        }
    }
}

// ---------------------------------------------------------------------------
// Launch
// ---------------------------------------------------------------------------
extern "C" void kernel_launch(void* const* d_in, const int* in_sizes, int n_in,
                              void* d_out, int out_size) {
    const float* x  = (const float*)d_in[0];
    const float* Wq = (const float*)d_in[1];
    const float* bq = (const float*)d_in[2];
    const float* Wk = (const float*)d_in[3];
    const float* bk = (const float*)d_in[4];
    const float* Wv = (const float*)d_in[5];
    const float* bv = (const float*)d_in[6];
    const float* Wp = (const float*)d_in[7];
    const float* bp = (const float*)d_in[8];
    float* out = (float*)d_out;

    __half* Wh;
    cudaGetSymbolAddress((void**)&Wh, g_Wh);

    cudaFuncSetAttribute((const void*)fused_kernel,
                         cudaFuncAttributeMaxDynamicSharedMemorySize, SMEM_BYTES);

    prep_kernel<<<64, 256>>>(Wq, bq, Wk, bk, bv);
    w2h_kernel<<<256, 256>>>(Wq, Wk, Wv, Wp);

    fused_kernel<<<2048, 512, SMEM_BYTES>>>(x, Wh, bp, out);
}

// round 10
// speedup vs baseline: 2.1003x; 1.1400x over previous
#include <cuda_runtime.h>
#include <cuda_fp16.h>
#include <cstdint>

// Fixed shapes: B=8, H=W=128, C=256, heads=8, hd=32, ws=8
#define NTOK  131072

// device-global scratch (allocation-free rule)
__device__ __half g_Wh[4 * 256 * 256];        // fp16 weights: q,k,v,p
__device__ float  g_Wt[2][256][256];          // fp32 transposed Wq, Wk (k-major) for prep
__device__ __half g_tabh[3][64][256];         // fp16: pe@Wq^T+bq, pe@Wk^T+bk, bv

// ---------------------------------------------------------------------------
// helpers
// ---------------------------------------------------------------------------
__device__ __forceinline__ void mma_f16(float& c0, float& c1, float& c2, float& c3,
                                        uint32_t a0, uint32_t a1, uint32_t a2, uint32_t a3,
                                        uint32_t b0, uint32_t b1) {
    asm volatile(
        "mma.sync.aligned.m16n8k16.row.col.f32.f16.f16.f32 "
        "{%0,%1,%2,%3}, {%4,%5,%6,%7}, {%8,%9}, {%0,%1,%2,%3};\n"
        : "+f"(c0), "+f"(c1), "+f"(c2), "+f"(c3)
        : "r"(a0), "r"(a1), "r"(a2), "r"(a3), "r"(b0), "r"(b1));
}

__device__ __forceinline__ void ldsm4(uint32_t& r0, uint32_t& r1, uint32_t& r2, uint32_t& r3,
                                      uint32_t addr) {
    asm volatile("ldmatrix.sync.aligned.m8n8.x4.shared.b16 {%0,%1,%2,%3}, [%4];"
                 : "=r"(r0), "=r"(r1), "=r"(r2), "=r"(r3) : "r"(addr));
}

__device__ __forceinline__ void ldsm4t(uint32_t& r0, uint32_t& r1, uint32_t& r2, uint32_t& r3,
                                       uint32_t addr) {
    asm volatile("ldmatrix.sync.aligned.m8n8.x4.trans.shared.b16 {%0,%1,%2,%3}, [%4];"
                 : "=r"(r0), "=r"(r1), "=r"(r2), "=r"(r3) : "r"(addr));
}

__device__ __forceinline__ uint32_t smem_u32(const void* p) {
    uint32_t a;
    asm("{ .reg .u64 t; cvta.to.shared.u64 t, %1; cvt.u32.u64 %0, t; }" : "=r"(a) : "l"(p));
    return a;
}

__device__ __forceinline__ uint32_t pack_h2(float lo, float hi) {
    __half2 h = __floats2half2_rn(lo, hi);
    return *(uint32_t*)&h;
}

__device__ __forceinline__ void cp16(uint32_t smem, const void* gmem) {
    asm volatile("cp.async.cg.shared.global [%0], [%1], 16;" :: "r"(smem), "l"(gmem));
}

// ---------------------------------------------------------------------------
// w2h: fp32 -> fp16 weights [q,k,v,p]; also fp32 transposed Wq/Wk for prep
// ---------------------------------------------------------------------------
__global__ void w2h_kernel(const float* __restrict__ Wq, const float* __restrict__ Wk,
                           const float* __restrict__ Wv, const float* __restrict__ Wp) {
    int gid = blockIdx.x * 256 + threadIdx.x;       // 0..65535
    int mat = gid >> 14;
    int off = (gid & 16383) << 2;
    const float* W = (mat == 0) ? Wq : (mat == 1) ? Wk : (mat == 2) ? Wv : Wp;
    float4 v = *(const float4*)(W + off);
    __half2 h0 = __floats2half2_rn(v.x, v.y);
    __half2 h1 = __floats2half2_rn(v.z, v.w);
    *(uint2*)(g_Wh + (size_t)mat * 65536 + off) = make_uint2(*(uint32_t*)&h0, *(uint32_t*)&h1);
    if (mat < 2) {                                  // transpose for prep (k-major)
        int r = off >> 8;                           // output-channel row n
        int c = off & 255;                          // k column
        g_Wt[mat][c + 0][r] = v.x;
        g_Wt[mat][c + 1][r] = v.y;
        g_Wt[mat][c + 2][r] = v.z;
        g_Wt[mat][c + 3][r] = v.w;
    }
}

// ---------------------------------------------------------------------------
// prep: g_tabh[0] = pe@Wq^T+bq, [1] = pe@Wk^T+bk, [2] = bv  (fp16)
// Reads transposed weights -> coalesced (thread = n, loop = k).
// ---------------------------------------------------------------------------
__global__ void prep_kernel(const float* __restrict__ bq, const float* __restrict__ bk,
                            const float* __restrict__ bv) {
    __shared__ float per[256];
    int p = blockIdx.x, n = threadIdx.x;
    int wy = p >> 3, wx = p & 7;
    {
        int f = n & 63, quad = n >> 6;
        float coord = (quad < 2) ? (float)wx : (float)wy;
        float arg = 3.14f * coord * (float)f * (1.0f / 200.0f);
        per[n] = (quad & 1) ? cosf(arg) : sinf(arg);
    }
    __syncthreads();
    float sq = bq[n], sk = bk[n];
#pragma unroll 8
    for (int k = 0; k < 256; k++) {
        float pv = per[k];
        sq = fmaf(pv, g_Wt[0][k][n], sq);
        sk = fmaf(pv, g_Wt[1][k][n], sk);
    }
    g_tabh[0][p][n] = __float2half_rn(sq);
    g_tabh[1][p][n] = __float2half_rn(sk);
    g_tabh[2][p][n] = __float2half_rn(bv[n]);
}

// ---------------------------------------------------------------------------
// Fused kernel: one block per window (64 tokens), 512 threads / 16 warps.
// warp = (mi = warp&1 -> 32 query rows, hn = warp>>1 -> head / 32-col slice).
// Phases: stage x -> GEMM K -> GEMM V -> GEMM Q (regs) -> attention -> O to
// smem -> GEMM proj -> out.  Weights stream via cp.async (L2-resident).
// ---------------------------------------------------------------------------
#define AHS 264                   // halves; row stride of As/Ks/Vs
#define BHS 72                    // halves; weight-chunk row stride
#define OFF_K  33792u             // 64*264*2
#define OFF_V  67584u
#define OFF_B  101376u            // + 64*264*2
#define SMEM_BYTES 175104u        // + 2*256*72*2

__global__ void __launch_bounds__(512, 1) fused_kernel(
        const float* __restrict__ x, const __half* __restrict__ Wh,
        const float* __restrict__ bp, float* __restrict__ out) {
    extern __shared__ char smc[];
    __half* As = (__half*)smc;            // x tile, later O tile
    uint32_t smb = smem_u32(smc);

    int tid = threadIdx.x, lane = tid & 31, warp = tid >> 5;
    int mi = warp & 1, hn = warp >> 1;
    int lr = lane & 15, lc8 = (lane >> 4) << 3;
    int lq = lane >> 2, kb2 = (lane & 3) << 1;

    int win = blockIdx.x;
    int bi = win >> 8, wl = win & 255;
    int wyi = wl >> 4, wxi = wl & 15;
    long base = (long)bi * 16384 + (wyi * 8) * 128 + wxi * 8;   // + (t>>3)*128 + (t&7)

    // ---- stage x window tile (64 x 256 fp32 -> fp16 smem) ----
#pragma unroll
    for (int i = 0; i < 8; i++) {
        int f = tid + i * 512;            // 0..4095
        int t = f >> 6;
        int c4 = (f & 63) << 2;
        long gr = base + (t >> 3) * 128 + (t & 7);
        float4 v = *(const float4*)(x + gr * 256 + c4);
        __half2 h0 = __floats2half2_rn(v.x, v.y);
        __half2 h1 = __floats2half2_rn(v.z, v.w);
        *(uint2*)(As + t * AHS + c4) = make_uint2(*(uint32_t*)&h0, *(uint32_t*)&h1);
    }
    // (ordered by the barrier inside the first run_gemm)

    // ---- shared GEMM mainloop: acc[mf][ni] = A[rows mi*32..] @ Wm[cols hn*32..]^T
    auto run_gemm = [&](const __half* Wm, float (&acc)[2][4][4]) {
#pragma unroll
        for (int a = 0; a < 2; a++)
#pragma unroll
            for (int b = 0; b < 4; b++)
#pragma unroll
                for (int r = 0; r < 4; r++) acc[a][b][r] = 0.f;
        // issue chunk 0 (256 rows x 64 halves = 8 x 16B segs per row)
#pragma unroll
        for (int i = 0; i < 4; i++) {
            int f = tid + i * 512;        // 0..2047
            int row = f >> 3, seg = f & 7;
            cp16(smb + OFF_B + (uint32_t)(row * BHS + seg * 8) * 2,
                 Wm + (size_t)row * 256 + seg * 8);
        }
        asm volatile("cp.async.commit_group;");
        asm volatile("cp.async.wait_group 0;");
        __syncthreads();

        for (int c = 0; c < 4; c++) {
            int buf = c & 1;
            if (c < 3) {
                int k0 = (c + 1) * 64;
#pragma unroll
                for (int i = 0; i < 4; i++) {
                    int f = tid + i * 512;
                    int row = f >> 3, seg = f & 7;
                    cp16(smb + OFF_B +
                         (uint32_t)((buf ^ 1) * 256 * BHS + row * BHS + seg * 8) * 2,
                         Wm + (size_t)row * 256 + k0 + seg * 8);
                }
                asm volatile("cp.async.commit_group;");
            }
            uint32_t bB = smb + OFF_B + (uint32_t)buf * (256 * BHS * 2);
#pragma unroll
            for (int kt = 0; kt < 4; kt++) {
                int kcol = c * 64 + kt * 16 + lc8;
                uint32_t af[2][4];
#pragma unroll
                for (int mf = 0; mf < 2; mf++)
                    ldsm4(af[mf][0], af[mf][1], af[mf][2], af[mf][3],
                          smb + (uint32_t)(((mi * 32 + mf * 16 + lr) * AHS + kcol) * 2));
                uint32_t bf[4][2];
#pragma unroll
                for (int ntp = 0; ntp < 2; ntp++) {
                    uint32_t r0, r1, r2, r3;
                    ldsm4(r0, r1, r2, r3,
                          bB + (uint32_t)(((hn * 32 + ntp * 16 + lr) * BHS + kt * 16 + lc8) * 2));
                    bf[ntp * 2][0] = r0; bf[ntp * 2][1] = r2;
                    bf[ntp * 2 + 1][0] = r1; bf[ntp * 2 + 1][1] = r3;
                }
#pragma unroll
                for (int mf = 0; mf < 2; mf++)
#pragma unroll
                    for (int ni = 0; ni < 4; ni++)
                        mma_f16(acc[mf][ni][0], acc[mf][ni][1], acc[mf][ni][2], acc[mf][ni][3],
                                af[mf][0], af[mf][1], af[mf][2], af[mf][3],
                                bf[ni][0], bf[ni][1]);
            }
            if (c < 3) asm volatile("cp.async.wait_group 0;");
            __syncthreads();
        }
    };

    // C-frag + fp16 table -> smem (used for K and V)
    auto store_kv = [&](float (&acc)[2][4][4], const __half* tab, uint32_t dstOff) {
#pragma unroll
        for (int mf = 0; mf < 2; mf++) {
            int r = mi * 32 + mf * 16 + lq;
#pragma unroll
            for (int ni = 0; ni < 4; ni++) {
                int cb = hn * 32 + ni * 8 + kb2;
                float2 t0 = __half22float2(*(const __half2*)&tab[r * 256 + cb]);
                float2 t1 = __half22float2(*(const __half2*)&tab[(r + 8) * 256 + cb]);
                *(uint32_t*)(smc + dstOff + (uint32_t)((r * AHS + cb) * 2)) =
                    pack_h2(acc[mf][ni][0] + t0.x, acc[mf][ni][1] + t0.y);
                *(uint32_t*)(smc + dstOff + (uint32_t)(((r + 8) * AHS + cb) * 2)) =
                    pack_h2(acc[mf][ni][2] + t1.x, acc[mf][ni][3] + t1.y);
            }
        }
    };

    float acc[2][4][4];

    // ---- K, V ----
    run_gemm(Wh + 65536, acc);                     // Wk
    store_kv(acc, &g_tabh[1][0][0], OFF_K);
    run_gemm(Wh + 131072, acc);                    // Wv
    store_kv(acc, &g_tabh[2][0][0], OFF_V);

    // ---- Q (stays in registers as mma A-frags, scale folded) ----
    run_gemm(Wh, acc);                             // Wq
    uint32_t afQ[2][2][4];
    {
        const __half* tq = &g_tabh[0][0][0];
        const float s = 0.17677669529663687f;      // 1/sqrt(32)
#pragma unroll
        for (int mf = 0; mf < 2; mf++) {
            int r = mi * 32 + mf * 16 + lq;
#pragma unroll
            for (int kf = 0; kf < 2; kf++) {
#pragma unroll
                for (int h = 0; h < 2; h++) {
                    int ni = 2 * kf + h;
                    int cb = hn * 32 + ni * 8 + kb2;
                    float2 t0 = __half22float2(*(const __half2*)&tq[r * 256 + cb]);
                    float2 t1 = __half22float2(*(const __half2*)&tq[(r + 8) * 256 + cb]);
                    afQ[mf][kf][2 * h] =
                        pack_h2((acc[mf][ni][0] + t0.x) * s, (acc[mf][ni][1] + t0.y) * s);
                    afQ[mf][kf][2 * h + 1] =
                        pack_h2((acc[mf][ni][2] + t1.x) * s, (acc[mf][ni][3] + t1.y) * s);
                }
            }
        }
    }

    // ---- S = Q K^T (32 rows x 64 keys per warp) ----
    float sc[2][8][4];
#pragma unroll
    for (int mf = 0; mf < 2; mf++)
#pragma unroll
        for (int nf = 0; nf < 8; nf++)
#pragma unroll
            for (int r = 0; r < 4; r++) sc[mf][nf][r] = 0.f;

#pragma unroll
    for (int kt = 0; kt < 2; kt++) {
#pragma unroll
        for (int nt = 0; nt < 4; nt++) {
            uint32_t b0, b1, b2, b3;
            ldsm4(b0, b1, b2, b3,
                  smb + OFF_K + (uint32_t)(((nt * 16 + lr) * AHS + hn * 32 + kt * 16 + lc8) * 2));
#pragma unroll
            for (int mf = 0; mf < 2; mf++) {
                mma_f16(sc[mf][nt * 2][0], sc[mf][nt * 2][1], sc[mf][nt * 2][2], sc[mf][nt * 2][3],
                        afQ[mf][kt][0], afQ[mf][kt][1], afQ[mf][kt][2], afQ[mf][kt][3], b0, b2);
                mma_f16(sc[mf][nt * 2 + 1][0], sc[mf][nt * 2 + 1][1],
                        sc[mf][nt * 2 + 1][2], sc[mf][nt * 2 + 1][3],
                        afQ[mf][kt][0], afQ[mf][kt][1], afQ[mf][kt][2], afQ[mf][kt][3], b1, b3);
            }
        }
    }

    // ---- softmax + P pack (scale already folded into Q) ----
    uint32_t pa[2][4][4];
#pragma unroll
    for (int mf = 0; mf < 2; mf++) {
        float m0 = -1e30f, m1 = -1e30f;
#pragma unroll
        for (int nf = 0; nf < 8; nf++) {
            m0 = fmaxf(m0, fmaxf(sc[mf][nf][0], sc[mf][nf][1]));
            m1 = fmaxf(m1, fmaxf(sc[mf][nf][2], sc[mf][nf][3]));
        }
        m0 = fmaxf(m0, __shfl_xor_sync(0xffffffffu, m0, 1));
        m0 = fmaxf(m0, __shfl_xor_sync(0xffffffffu, m0, 2));
        m1 = fmaxf(m1, __shfl_xor_sync(0xffffffffu, m1, 1));
        m1 = fmaxf(m1, __shfl_xor_sync(0xffffffffu, m1, 2));
        float s0 = 0.f, s1 = 0.f;
#pragma unroll
        for (int nf = 0; nf < 8; nf++) {
            sc[mf][nf][0] = __expf(sc[mf][nf][0] - m0);
            sc[mf][nf][1] = __expf(sc[mf][nf][1] - m0);
            sc[mf][nf][2] = __expf(sc[mf][nf][2] - m1);
            sc[mf][nf][3] = __expf(sc[mf][nf][3] - m1);
            s0 += sc[mf][nf][0] + sc[mf][nf][1];
            s1 += sc[mf][nf][2] + sc[mf][nf][3];
        }
        s0 += __shfl_xor_sync(0xffffffffu, s0, 1);
        s0 += __shfl_xor_sync(0xffffffffu, s0, 2);
        s1 += __shfl_xor_sync(0xffffffffu, s1, 1);
        s1 += __shfl_xor_sync(0xffffffffu, s1, 2);
        float inv0 = 1.0f / s0, inv1 = 1.0f / s1;
#pragma unroll
        for (int kf = 0; kf < 4; kf++) {
            pa[mf][kf][0] = pack_h2(sc[mf][2 * kf][0] * inv0, sc[mf][2 * kf][1] * inv0);
            pa[mf][kf][1] = pack_h2(sc[mf][2 * kf][2] * inv1, sc[mf][2 * kf][3] * inv1);
            pa[mf][kf][2] = pack_h2(sc[mf][2 * kf + 1][0] * inv0, sc[mf][2 * kf + 1][1] * inv0);
            pa[mf][kf][3] = pack_h2(sc[mf][2 * kf + 1][2] * inv1, sc[mf][2 * kf + 1][3] * inv1);
        }
    }

    // ---- O = P V ----
    float oc[2][4][4];
#pragma unroll
    for (int mf = 0; mf < 2; mf++)
#pragma unroll
        for (int nf = 0; nf < 4; nf++)
#pragma unroll
            for (int r = 0; r < 4; r++) oc[mf][nf][r] = 0.f;

#pragma unroll
    for (int kf = 0; kf < 4; kf++) {
#pragma unroll
        for (int tt = 0; tt < 2; tt++) {
            uint32_t b0, b1, b2, b3;
            ldsm4t(b0, b1, b2, b3,
                   smb + OFF_V + (uint32_t)(((kf * 16 + lr) * AHS + hn * 32 + tt * 16 + lc8) * 2));
#pragma unroll
            for (int mf = 0; mf < 2; mf++) {
                mma_f16(oc[mf][tt * 2][0], oc[mf][tt * 2][1], oc[mf][tt * 2][2], oc[mf][tt * 2][3],
                        pa[mf][kf][0], pa[mf][kf][1], pa[mf][kf][2], pa[mf][kf][3], b0, b1);
                mma_f16(oc[mf][tt * 2 + 1][0], oc[mf][tt * 2 + 1][1],
                        oc[mf][tt * 2 + 1][2], oc[mf][tt * 2 + 1][3],
                        pa[mf][kf][0], pa[mf][kf][1], pa[mf][kf][2], pa[mf][kf][3], b2, b3);
            }
        }
    }

    // ---- store O into the dead x-tile buffer ----
#pragma unroll
    for (int mf = 0; mf < 2; mf++) {
        int r = mi * 32 + mf * 16 + lq;
#pragma unroll
        for (int ni = 0; ni < 4; ni++) {
            int cb = hn * 32 + ni * 8 + kb2;
            *(uint32_t*)(As + r * AHS + cb) = pack_h2(oc[mf][ni][0], oc[mf][ni][1]);
            *(uint32_t*)(As + (r + 8) * AHS + cb) = pack_h2(oc[mf][ni][2], oc[mf][ni][3]);
        }
    }

    // ---- projection: out = O @ Wp^T + bp (barrier inside run_gemm orders O stores) ----
    run_gemm(Wh + 196608, acc);                    // Wp
#pragma unroll
    for (int mf = 0; mf < 2; mf++) {
        int r = mi * 32 + mf * 16 + lq;
        long gr0 = base + (r >> 3) * 128 + (r & 7);
        long gr1 = base + ((r + 8) >> 3) * 128 + ((r + 8) & 7);
#pragma unroll
        for (int ni = 0; ni < 4; ni++) {
            int cb = hn * 32 + ni * 8 + kb2;
            float b0 = __ldg(bp + cb), b1 = __ldg(bp + cb + 1);
            *(float2*)(out + gr0 * 256 + cb) =
                make_float2(acc[mf][ni][0] + b0, acc[mf][ni][1] + b1);
            *(float2*)(out + gr1 * 256 + cb) =
                make_float2(acc[mf][ni][2] + b0, acc[mf][ni][3] + b1);
        }
    }
}

// ---------------------------------------------------------------------------
// Launch
// ---------------------------------------------------------------------------
extern "C" void kernel_launch(void* const* d_in, const int* in_sizes, int n_in,
                              void* d_out, int out_size) {
    const float* x  = (const float*)d_in[0];
    const float* Wq = (const float*)d_in[1];
    const float* bq = (const float*)d_in[2];
    const float* Wk = (const float*)d_in[3];
    const float* bk = (const float*)d_in[4];
    const float* Wv = (const float*)d_in[5];
    const float* bv = (const float*)d_in[6];
    const float* Wp = (const float*)d_in[7];
    const float* bp = (const float*)d_in[8];
    float* out = (float*)d_out;

    __half* Wh;
    cudaGetSymbolAddress((void**)&Wh, g_Wh);

    cudaFuncSetAttribute((const void*)fused_kernel,
                         cudaFuncAttributeMaxDynamicSharedMemorySize, SMEM_BYTES);

    w2h_kernel<<<256, 256>>>(Wq, Wk, Wv, Wp);          // also builds transposed Wq/Wk
    prep_kernel<<<64, 256>>>(bq, bk, bv);              // coalesced via g_Wt

    fused_kernel<<<2048, 512, SMEM_BYTES>>>(x, Wh, bp, out);
}